// round 2
// baseline (speedup 1.0000x reference)
#include <cuda_runtime.h>
#include <math.h>

#define NN   100000
#define NE   640000
#define DD   128
#define NG   512

// ---------------- scratch (no allocations allowed) ----------------
__device__ float g_bufA[(size_t)NN * DD];   // agg ping
__device__ float g_bufB[(size_t)NN * DD];   // agg pong
__device__ float g_hw  [(size_t)NN * DD];   // h @ W
__device__ float g_dinv[NN];
__device__ int   g_deg [NN];
__device__ float g_pooled[NG * DD];
__device__ float g_z1[NG * DD];
__device__ float g_z2[NG * DD];

// ---------------- degree / norm ----------------
__global__ void k_deg_init() {
    int n = blockIdx.x * blockDim.x + threadIdx.x;
    if (n < NN) g_deg[n] = 1;   // self loop
}
__global__ void k_deg_count(const int* __restrict__ dst) {
    int e = blockIdx.x * blockDim.x + threadIdx.x;
    if (e < NE) atomicAdd(&g_deg[dst[e]], 1);
}
__global__ void k_dinv() {
    int n = blockIdx.x * blockDim.x + threadIdx.x;
    if (n < NN) g_dinv[n] = rsqrtf((float)g_deg[n]);
}

// ---------------- GEMM: out[M,128] = act(in)[M,128] @ W[128,128] ----------------
// act(v, k) = fuse ? max(v + bias[k], 0) : v   (bias/relu of PREVIOUS layer fused on load)
__global__ __launch_bounds__(256) void k_gemm_act(
    const float* __restrict__ A, const float* __restrict__ W,
    const float* __restrict__ bias, float* __restrict__ out, int M, int fuse)
{
    __shared__ float As[16][128];
    __shared__ float Bs[16][128];
    int tid = threadIdx.x;
    int m0  = blockIdx.x * 128;
    int ty  = tid >> 4;        // 0..15
    int tx  = tid & 15;        // 0..15
    float acc[8][8];
    #pragma unroll
    for (int i = 0; i < 8; i++)
        #pragma unroll
        for (int j = 0; j < 8; j++) acc[i][j] = 0.f;

    for (int k0 = 0; k0 < 128; k0 += 16) {
        #pragma unroll
        for (int it = 0; it < 2; it++) {
            int idx = tid + it * 256;            // 0..511
            // A tile: 128 rows x 16 cols = 512 float4
            int ml = idx >> 2;                   // 0..127
            int c  = idx & 3;                    // which float4 in the 16-col strip
            int m  = m0 + ml;
            float4 v = make_float4(0.f, 0.f, 0.f, 0.f);
            if (m < M)
                v = *reinterpret_cast<const float4*>(&A[(size_t)m * 128 + k0 + c * 4]);
            if (fuse) {
                float4 b4 = *reinterpret_cast<const float4*>(&bias[k0 + c * 4]);
                v.x = fmaxf(v.x + b4.x, 0.f);
                v.y = fmaxf(v.y + b4.y, 0.f);
                v.z = fmaxf(v.z + b4.z, 0.f);
                v.w = fmaxf(v.w + b4.w, 0.f);
            }
            As[c * 4 + 0][ml] = v.x;
            As[c * 4 + 1][ml] = v.y;
            As[c * 4 + 2][ml] = v.z;
            As[c * 4 + 3][ml] = v.w;
            // W tile: 16 rows x 128 cols = 512 float4
            int kl = idx >> 5;                   // 0..15
            int nl = idx & 31;                   // 0..31 (float4 within row)
            *reinterpret_cast<float4*>(&Bs[kl][nl * 4]) =
                *reinterpret_cast<const float4*>(&W[(size_t)(k0 + kl) * 128 + nl * 4]);
        }
        __syncthreads();
        #pragma unroll
        for (int k = 0; k < 16; k++) {
            float4 a0 = *reinterpret_cast<const float4*>(&As[k][ty * 8]);
            float4 a1 = *reinterpret_cast<const float4*>(&As[k][ty * 8 + 4]);
            float4 b0 = *reinterpret_cast<const float4*>(&Bs[k][tx * 8]);
            float4 b1 = *reinterpret_cast<const float4*>(&Bs[k][tx * 8 + 4]);
            float a[8] = {a0.x, a0.y, a0.z, a0.w, a1.x, a1.y, a1.z, a1.w};
            float b[8] = {b0.x, b0.y, b0.z, b0.w, b1.x, b1.y, b1.z, b1.w};
            #pragma unroll
            for (int i = 0; i < 8; i++)
                #pragma unroll
                for (int j = 0; j < 8; j++)
                    acc[i][j] = fmaf(a[i], b[j], acc[i][j]);
        }
        __syncthreads();
    }
    #pragma unroll
    for (int i = 0; i < 8; i++) {
        int m = m0 + ty * 8 + i;
        if (m < M) {
            #pragma unroll
            for (int j = 0; j < 8; j += 4) {
                float4 v = make_float4(acc[i][j], acc[i][j+1], acc[i][j+2], acc[i][j+3]);
                *reinterpret_cast<float4*>(&out[(size_t)m * 128 + tx * 8 + j]) = v;
            }
        }
    }
}

// ---------------- aggregation ----------------
// agg[n] = hw[n] * dinv[n]^2  (self loop term, also serves as init)
__global__ void k_agg_self(const float* __restrict__ hw, float* __restrict__ agg) {
    int idx = blockIdx.x * blockDim.x + threadIdx.x;   // over NN*32 float4
    if (idx < NN * 32) {
        int n = idx >> 5;
        float w = g_dinv[n]; w = w * w;
        float4 v = reinterpret_cast<const float4*>(hw)[idx];
        v.x *= w; v.y *= w; v.z *= w; v.w *= w;
        reinterpret_cast<float4*>(agg)[idx] = v;
    }
}

// one warp per edge: gather hw[src] row (512B), scatter-add into agg[dst]
__global__ void k_edge_agg(const int* __restrict__ src,
                           const int* __restrict__ dst,
                           const float* __restrict__ hw,
                           float* __restrict__ agg)
{
    int gid  = blockIdx.x * blockDim.x + threadIdx.x;
    int e    = gid >> 5;
    int lane = threadIdx.x & 31;
    if (e >= NE) return;
    int s = src[e];
    int t = dst[e];
    float w = g_dinv[s] * g_dinv[t];
    float4 v = reinterpret_cast<const float4*>(hw)[s * 32 + lane];
    float* dp = &agg[(size_t)t * 128 + (lane << 2)];
    atomicAdd(dp + 0, v.x * w);
    atomicAdd(dp + 1, v.y * w);
    atomicAdd(dp + 2, v.z * w);
    atomicAdd(dp + 3, v.w * w);
}

// ---------------- pooling (batch is sorted) ----------------
__global__ void k_zero_pooled() {
    int i = blockIdx.x * blockDim.x + threadIdx.x;
    if (i < NG * DD) g_pooled[i] = 0.f;
}
// block = 128 threads (one per feature), handles 128 consecutive nodes,
// accumulating locally while graph id is unchanged (sorted batch => few atomics)
__global__ void k_pool(const float* __restrict__ h,
                       const int* __restrict__ batch,
                       const float* __restrict__ bias)
{
    int d  = threadIdx.x;
    int n0 = blockIdx.x * 128;
    int n1 = n0 + 128; if (n1 > NN) n1 = NN;
    if (n0 >= NN) return;
    float b   = bias[d];
    float acc = 0.f;
    int gprev = batch[n0];
    for (int n = n0; n < n1; n++) {
        int g = batch[n];
        if (g != gprev) {
            atomicAdd(&g_pooled[gprev * 128 + d], acc);
            acc = 0.f;
            gprev = g;
        }
        acc += fmaxf(h[(size_t)n * 128 + d] + b, 0.f);
    }
    atomicAdd(&g_pooled[gprev * 128 + d], acc);
}

// ---------------- MLP head ----------------
// out[512,128] = relu(in @ W + b); one block per row
__global__ void k_mlp(const float* __restrict__ in, const float* __restrict__ W,
                      const float* __restrict__ bias, float* __restrict__ out)
{
    __shared__ float row[128];
    int r = blockIdx.x, c = threadIdx.x;
    row[c] = in[r * 128 + c];
    __syncthreads();
    float acc = bias[c];
    #pragma unroll 8
    for (int k = 0; k < 128; k++)
        acc = fmaf(row[k], W[k * 128 + c], acc);
    out[r * 128 + c] = fmaxf(acc, 0.f);
}

__global__ void k_final(const float* __restrict__ z, const float* __restrict__ W3,
                        const float* __restrict__ b3, float* __restrict__ out)
{
    int g = blockIdx.x, t = threadIdx.x;
    float v = z[g * 128 + t] * W3[t];
    #pragma unroll
    for (int o = 16; o > 0; o >>= 1) v += __shfl_down_sync(0xffffffffu, v, o);
    __shared__ float partial[4];
    if ((t & 31) == 0) partial[t >> 5] = v;
    __syncthreads();
    if (t == 0) {
        float s = partial[0] + partial[1] + partial[2] + partial[3] + b3[0];
        out[g] = 1.f / (1.f + expf(-s));
    }
}

// ---------------- launch ----------------
extern "C" void kernel_launch(void* const* d_in, const int* in_sizes, int n_in,
                              void* d_out, int out_size)
{
    const float* x     = (const float*)d_in[0];
    const int*   ei    = (const int*)d_in[1];     // int32 (JAX default x64 disabled)
    const int*   src   = ei;
    const int*   dst   = ei + NE;
    const int*   batch = (const int*)d_in[2];     // int32
    const float* convW = (const float*)d_in[3];
    const float* convB = (const float*)d_in[4];
    const float* W1    = (const float*)d_in[5];
    const float* b1    = (const float*)d_in[6];
    const float* W2    = (const float*)d_in[7];
    const float* b2    = (const float*)d_in[8];
    const float* W3    = (const float*)d_in[9];
    const float* b3    = (const float*)d_in[10];
    float* out = (float*)d_out;

    float *bufA, *bufB, *hw, *pooled, *z1, *z2;
    cudaGetSymbolAddress((void**)&bufA,   g_bufA);
    cudaGetSymbolAddress((void**)&bufB,   g_bufB);
    cudaGetSymbolAddress((void**)&hw,     g_hw);
    cudaGetSymbolAddress((void**)&pooled, g_pooled);
    cudaGetSymbolAddress((void**)&z1,     g_z1);
    cudaGetSymbolAddress((void**)&z2,     g_z2);

    k_deg_init <<<(NN + 255) / 256, 256>>>();
    k_deg_count<<<(NE + 255) / 256, 256>>>(dst);
    k_dinv     <<<(NN + 255) / 256, 256>>>();

    const float* hin = x;
    float* aggbuf[4] = {bufA, bufB, bufA, bufB};
    for (int l = 0; l < 4; l++) {
        const float* bias_prev = convB + (l > 0 ? (l - 1) * DD : 0);
        k_gemm_act<<<(NN + 127) / 128, 256>>>(hin, convW + (size_t)l * DD * DD,
                                              bias_prev, hw, NN, l > 0 ? 1 : 0);
        float* agg = aggbuf[l];
        k_agg_self<<<(NN * 32 + 255) / 256, 256>>>(hw, agg);
        k_edge_agg<<<(NE * 32 + 255) / 256, 256>>>(src, dst, hw, agg);
        hin = agg;
    }

    k_zero_pooled<<<(NG * DD + 255) / 256, 256>>>();
    k_pool<<<(NN + 127) / 128, 128>>>(hin, batch, convB + 3 * DD);
    k_mlp<<<NG, 128>>>(pooled, W1, b1, z1);
    k_mlp<<<NG, 128>>>(z1, W2, b2, z2);
    k_final<<<NG, 128>>>(z2, W3, b3, out);
}

// round 3
// speedup vs baseline: 1.9533x; 1.9533x over previous
#include <cuda_runtime.h>
#include <math.h>

#define NN   100000
#define NE   640000
#define DD   128
#define NG   512
#define SCAN_B 1024
#define NSB  ((NN + SCAN_B - 1) / SCAN_B)   // 98 scan blocks

// ---------------- scratch (no allocations allowed) ----------------
__device__ float g_bufA[(size_t)NN * DD];   // agg ping
__device__ float g_bufB[(size_t)NN * DD];   // agg pong
__device__ float g_hw  [(size_t)NN * DD];   // h @ W
__device__ float g_dinv[NN];
__device__ float g_dinv2[NN];
__device__ int   g_cnt [NN];                // in-degree (without self loop)
__device__ int   g_off [NN + 1];            // CSR offsets
__device__ int   g_cursor[NN];              // scatter cursors
__device__ int   g_csrc[NE];                // CSR src ids
__device__ float g_cw  [NE];                // CSR edge weights dinv[s]*dinv[t]
__device__ int   g_bsum[NSB];               // scan block sums
__device__ int   g_bpre[NSB];               // scanned block sums
__device__ float g_pooled[NG * DD];
__device__ float g_z1[NG * DD];
__device__ float g_z2[NG * DD];

// ---------------- degree / norm ----------------
__global__ void k_cnt_zero() {
    int n = blockIdx.x * blockDim.x + threadIdx.x;
    if (n < NN) g_cnt[n] = 0;
}
__global__ void k_cnt(const int* __restrict__ dst) {
    int e = blockIdx.x * blockDim.x + threadIdx.x;
    if (e < NE) atomicAdd(&g_cnt[dst[e]], 1);
}
__global__ void k_dinv() {
    int n = blockIdx.x * blockDim.x + threadIdx.x;
    if (n < NN) {
        float deg = (float)(g_cnt[n] + 1);   // + self loop
        g_dinv[n]  = rsqrtf(deg);
        g_dinv2[n] = 1.0f / deg;
    }
}

// ---------------- scan (CSR offsets) ----------------
__global__ __launch_bounds__(SCAN_B) void k_scan1() {
    __shared__ int s[SCAN_B];
    int t = threadIdx.x;
    int i = blockIdx.x * SCAN_B + t;
    int v = (i < NN) ? g_cnt[i] : 0;
    s[t] = v;
    __syncthreads();
    #pragma unroll
    for (int o = 1; o < SCAN_B; o <<= 1) {
        int x = (t >= o) ? s[t - o] : 0;
        __syncthreads();
        s[t] += x;
        __syncthreads();
    }
    if (i < NN) g_cnt[i] = s[t];             // reuse g_cnt as inclusive-scan-in-block
    if (t == SCAN_B - 1) g_bsum[blockIdx.x] = s[t];
}
__global__ void k_scan2() {
    if (threadIdx.x == 0) {
        int acc = 0;
        for (int b = 0; b < NSB; b++) { g_bpre[b] = acc; acc += g_bsum[b]; }
    }
}
__global__ __launch_bounds__(SCAN_B) void k_scan3() {
    int i = blockIdx.x * SCAN_B + threadIdx.x;
    if (i < NN) {
        int incl = g_cnt[i] + g_bpre[blockIdx.x];
        g_off[i + 1] = incl;
        if (i == 0) g_off[0] = 0;
    }
}
__global__ void k_cursor_init() {
    int n = blockIdx.x * blockDim.x + threadIdx.x;
    if (n < NN) g_cursor[n] = g_off[n];
}
__global__ void k_scatter(const int* __restrict__ src, const int* __restrict__ dst) {
    int e = blockIdx.x * blockDim.x + threadIdx.x;
    if (e < NE) {
        int s = src[e], t = dst[e];
        int p = atomicAdd(&g_cursor[t], 1);
        g_csrc[p] = s;
        g_cw[p]   = g_dinv[s] * g_dinv[t];
    }
}

// ---------------- GEMM: out[M,128] = act(in)[M,128] @ W[128,128] ----------------
__global__ __launch_bounds__(256) void k_gemm_act(
    const float* __restrict__ A, const float* __restrict__ W,
    const float* __restrict__ bias, float* __restrict__ out, int M, int fuse)
{
    __shared__ float As[16][128];
    __shared__ float Bs[16][128];
    int tid = threadIdx.x;
    int m0  = blockIdx.x * 128;
    int ty  = tid >> 4;
    int tx  = tid & 15;
    float acc[8][8];
    #pragma unroll
    for (int i = 0; i < 8; i++)
        #pragma unroll
        for (int j = 0; j < 8; j++) acc[i][j] = 0.f;

    for (int k0 = 0; k0 < 128; k0 += 16) {
        #pragma unroll
        for (int it = 0; it < 2; it++) {
            int idx = tid + it * 256;
            int ml = idx >> 2;
            int c  = idx & 3;
            int m  = m0 + ml;
            float4 v = make_float4(0.f, 0.f, 0.f, 0.f);
            if (m < M)
                v = *reinterpret_cast<const float4*>(&A[(size_t)m * 128 + k0 + c * 4]);
            if (fuse) {
                float4 b4 = *reinterpret_cast<const float4*>(&bias[k0 + c * 4]);
                v.x = fmaxf(v.x + b4.x, 0.f);
                v.y = fmaxf(v.y + b4.y, 0.f);
                v.z = fmaxf(v.z + b4.z, 0.f);
                v.w = fmaxf(v.w + b4.w, 0.f);
            }
            As[c * 4 + 0][ml] = v.x;
            As[c * 4 + 1][ml] = v.y;
            As[c * 4 + 2][ml] = v.z;
            As[c * 4 + 3][ml] = v.w;
            int kl = idx >> 5;
            int nl = idx & 31;
            *reinterpret_cast<float4*>(&Bs[kl][nl * 4]) =
                *reinterpret_cast<const float4*>(&W[(size_t)(k0 + kl) * 128 + nl * 4]);
        }
        __syncthreads();
        #pragma unroll
        for (int k = 0; k < 16; k++) {
            float4 a0 = *reinterpret_cast<const float4*>(&As[k][ty * 8]);
            float4 a1 = *reinterpret_cast<const float4*>(&As[k][ty * 8 + 4]);
            float4 b0 = *reinterpret_cast<const float4*>(&Bs[k][tx * 8]);
            float4 b1 = *reinterpret_cast<const float4*>(&Bs[k][tx * 8 + 4]);
            float a[8] = {a0.x, a0.y, a0.z, a0.w, a1.x, a1.y, a1.z, a1.w};
            float b[8] = {b0.x, b0.y, b0.z, b0.w, b1.x, b1.y, b1.z, b1.w};
            #pragma unroll
            for (int i = 0; i < 8; i++)
                #pragma unroll
                for (int j = 0; j < 8; j++)
                    acc[i][j] = fmaf(a[i], b[j], acc[i][j]);
        }
        __syncthreads();
    }
    #pragma unroll
    for (int i = 0; i < 8; i++) {
        int m = m0 + ty * 8 + i;
        if (m < M) {
            #pragma unroll
            for (int j = 0; j < 8; j += 4) {
                float4 v = make_float4(acc[i][j], acc[i][j+1], acc[i][j+2], acc[i][j+3]);
                *reinterpret_cast<float4*>(&out[(size_t)m * 128 + tx * 8 + j]) = v;
            }
        }
    }
}

// ---------------- CSR aggregation: one warp per node, no atomics ----------------
// agg[n] = dinv2[n]*hw[n] + sum_{e: dst=n} w_e * hw[src_e]
__global__ __launch_bounds__(256) void k_agg_csr(const float* __restrict__ hw,
                                                 float* __restrict__ agg)
{
    int gid  = blockIdx.x * blockDim.x + threadIdx.x;
    int n    = gid >> 5;
    int lane = threadIdx.x & 31;
    if (n >= NN) return;
    const float4* hw4 = reinterpret_cast<const float4*>(hw);
    float4 a = hw4[(size_t)n * 32 + lane];
    float s = g_dinv2[n];
    float4 acc = make_float4(a.x * s, a.y * s, a.z * s, a.w * s);
    int beg = g_off[n], end = g_off[n + 1];
    for (int i = beg; i < end; i++) {
        int   sn = g_csrc[i];
        float w  = g_cw[i];
        float4 v = __ldg(&hw4[(size_t)sn * 32 + lane]);
        acc.x = fmaf(w, v.x, acc.x);
        acc.y = fmaf(w, v.y, acc.y);
        acc.z = fmaf(w, v.z, acc.z);
        acc.w = fmaf(w, v.w, acc.w);
    }
    reinterpret_cast<float4*>(agg)[(size_t)n * 32 + lane] = acc;
}

// ---------------- pooling (batch is sorted) ----------------
__global__ void k_zero_pooled() {
    int i = blockIdx.x * blockDim.x + threadIdx.x;
    if (i < NG * DD) g_pooled[i] = 0.f;
}
__global__ void k_pool(const float* __restrict__ h,
                       const int* __restrict__ batch,
                       const float* __restrict__ bias)
{
    int d  = threadIdx.x;
    int n0 = blockIdx.x * 128;
    int n1 = n0 + 128; if (n1 > NN) n1 = NN;
    if (n0 >= NN) return;
    float b   = bias[d];
    float acc = 0.f;
    int gprev = batch[n0];
    for (int n = n0; n < n1; n++) {
        int g = batch[n];
        if (g != gprev) {
            atomicAdd(&g_pooled[gprev * 128 + d], acc);
            acc = 0.f;
            gprev = g;
        }
        acc += fmaxf(h[(size_t)n * 128 + d] + b, 0.f);
    }
    atomicAdd(&g_pooled[gprev * 128 + d], acc);
}

// ---------------- MLP head ----------------
__global__ void k_mlp(const float* __restrict__ in, const float* __restrict__ W,
                      const float* __restrict__ bias, float* __restrict__ out)
{
    __shared__ float row[128];
    int r = blockIdx.x, c = threadIdx.x;
    row[c] = in[r * 128 + c];
    __syncthreads();
    float acc = bias[c];
    #pragma unroll 8
    for (int k = 0; k < 128; k++)
        acc = fmaf(row[k], W[k * 128 + c], acc);
    out[r * 128 + c] = fmaxf(acc, 0.f);
}

__global__ void k_final(const float* __restrict__ z, const float* __restrict__ W3,
                        const float* __restrict__ b3, float* __restrict__ out)
{
    int g = blockIdx.x, t = threadIdx.x;
    float v = z[g * 128 + t] * W3[t];
    #pragma unroll
    for (int o = 16; o > 0; o >>= 1) v += __shfl_down_sync(0xffffffffu, v, o);
    __shared__ float partial[4];
    if ((t & 31) == 0) partial[t >> 5] = v;
    __syncthreads();
    if (t == 0) {
        float s = partial[0] + partial[1] + partial[2] + partial[3] + b3[0];
        out[g] = 1.f / (1.f + expf(-s));
    }
}

// ---------------- launch ----------------
extern "C" void kernel_launch(void* const* d_in, const int* in_sizes, int n_in,
                              void* d_out, int out_size)
{
    const float* x     = (const float*)d_in[0];
    const int*   ei    = (const int*)d_in[1];     // int32 (JAX x64 disabled)
    const int*   src   = ei;
    const int*   dst   = ei + NE;
    const int*   batch = (const int*)d_in[2];
    const float* convW = (const float*)d_in[3];
    const float* convB = (const float*)d_in[4];
    const float* W1    = (const float*)d_in[5];
    const float* b1    = (const float*)d_in[6];
    const float* W2    = (const float*)d_in[7];
    const float* b2    = (const float*)d_in[8];
    const float* W3    = (const float*)d_in[9];
    const float* b3    = (const float*)d_in[10];
    float* out = (float*)d_out;

    float *bufA, *bufB, *hw, *pooled, *z1, *z2;
    cudaGetSymbolAddress((void**)&bufA,   g_bufA);
    cudaGetSymbolAddress((void**)&bufB,   g_bufB);
    cudaGetSymbolAddress((void**)&hw,     g_hw);
    cudaGetSymbolAddress((void**)&pooled, g_pooled);
    cudaGetSymbolAddress((void**)&z1,     g_z1);
    cudaGetSymbolAddress((void**)&z2,     g_z2);

    // ---- CSR build (once per launch, reused by all 4 layers) ----
    k_cnt_zero   <<<(NN + 255) / 256, 256>>>();
    k_cnt        <<<(NE + 255) / 256, 256>>>(dst);
    k_dinv       <<<(NN + 255) / 256, 256>>>();
    k_scan1      <<<NSB, SCAN_B>>>();
    k_scan2      <<<1, 32>>>();
    k_scan3      <<<NSB, SCAN_B>>>();
    k_cursor_init<<<(NN + 255) / 256, 256>>>();
    k_scatter    <<<(NE + 255) / 256, 256>>>(src, dst);

    // ---- 4 GCN layers ----
    const float* hin = x;
    float* aggbuf[4] = {bufA, bufB, bufA, bufB};
    for (int l = 0; l < 4; l++) {
        const float* bias_prev = convB + (l > 0 ? (l - 1) * DD : 0);
        k_gemm_act<<<(NN + 127) / 128, 256>>>(hin, convW + (size_t)l * DD * DD,
                                              bias_prev, hw, NN, l > 0 ? 1 : 0);
        k_agg_csr<<<(NN * 32 + 255) / 256, 256>>>(hw, aggbuf[l]);
        hin = aggbuf[l];
    }

    // ---- pooling + MLP head ----
    k_zero_pooled<<<(NG * DD + 255) / 256, 256>>>();
    k_pool<<<(NN + 127) / 128, 128>>>(hin, batch, convB + 3 * DD);
    k_mlp<<<NG, 128>>>(pooled, W1, b1, z1);
    k_mlp<<<NG, 128>>>(z1, W2, b2, z2);
    k_final<<<NG, 128>>>(z2, W3, b3, out);
}

// round 5
// speedup vs baseline: 1.9724x; 1.0097x over previous
#include <cuda_runtime.h>
#include <cuda_bf16.h>
#include <math.h>
#include <cstdint>

#define NN   100000
#define NE   640000
#define DD   128
#define NG   512
#define SCAN_B 1024
#define NSB  ((NN + SCAN_B - 1) / SCAN_B)   // 98 scan blocks
#define NTILES ((NN + 127) / 128)           // 782

// ---------------- scratch (no allocations allowed) ----------------
__device__ float g_bufA[(size_t)NN * DD];
__device__ float g_bufB[(size_t)NN * DD];
__device__ float g_hw  [(size_t)NN * DD];
__device__ float g_dinv[NN];
__device__ float g_dinv2[NN];
__device__ int   g_cnt [NN];
__device__ int   g_off [NN + 1];
__device__ int   g_cursor[NN];
__device__ int   g_csrc[NE];
__device__ float g_cw  [NE];
__device__ int   g_bsum[NSB];
__device__ int   g_bpre[NSB];
__device__ float g_pooled[NG * DD];
__device__ float g_z1[NG * DD];
__device__ float g_z2[NG * DD];

// ---------------- smem layout for MMA GEMM (bytes) ----------------
// tiles are [128 rows][136 cols] bf16 (stride padded: 272B row = 17*16B)
#define TSTRIDE 136
#define TILE_B  (128 * TSTRIDE * 2)     // 34816
#define SM_AH 0
#define SM_AL (SM_AH + TILE_B)
#define SM_WH (SM_AL + TILE_B)
#define SM_WL (SM_WH + TILE_B)
#define SMEM_MMA (SM_WL + TILE_B)       // 139264

__device__ __forceinline__ uint32_t pack_bf16x2(float a, float b) {
    __nv_bfloat162 t(__float2bfloat16(a), __float2bfloat16(b));
    return *reinterpret_cast<uint32_t*>(&t);
}

__device__ __forceinline__ void mma_bf16(float c[4], uint32_t a0, uint32_t a1,
                                         uint32_t a2, uint32_t a3,
                                         uint32_t b0, uint32_t b1) {
    asm volatile(
        "mma.sync.aligned.m16n8k16.row.col.f32.bf16.bf16.f32 "
        "{%0,%1,%2,%3}, {%4,%5,%6,%7}, {%8,%9}, {%0,%1,%2,%3};"
        : "+f"(c[0]), "+f"(c[1]), "+f"(c[2]), "+f"(c[3])
        : "r"(a0), "r"(a1), "r"(a2), "r"(a3), "r"(b0), "r"(b1));
}

// ============ tensor-core GEMM via mma.sync: out[M,128] = act(A) @ W ============
// A,W split into bf16 hi+lo; accumulate hi*hi + hi*lo + lo*hi in fp32.
__global__ __launch_bounds__(256) void k_gemm_mma(
    const float* __restrict__ A, const float* __restrict__ W,
    const float* __restrict__ bias, float* __restrict__ out, int M, int fuse)
{
    extern __shared__ char smem[];
    int tid  = threadIdx.x;
    int wid  = tid >> 5;
    int lane = tid & 31;
    int m0   = blockIdx.x * 128;

    // ---- load + convert A tile (fused bias+relu of previous layer) ----
    #pragma unroll
    for (int it = 0; it < 16; it++) {
        int idx = tid + it * 256;          // 0..4095 float4s
        int r   = idx >> 5;                // 0..127
        int c4  = idx & 31;                // float4 within row
        int m   = m0 + r;
        float4 v = make_float4(0.f, 0.f, 0.f, 0.f);
        if (m < M) v = *reinterpret_cast<const float4*>(&A[(size_t)m * 128 + c4 * 4]);
        if (fuse) {
            float4 b4 = *reinterpret_cast<const float4*>(&bias[c4 * 4]);
            v.x = fmaxf(v.x + b4.x, 0.f); v.y = fmaxf(v.y + b4.y, 0.f);
            v.z = fmaxf(v.z + b4.z, 0.f); v.w = fmaxf(v.w + b4.w, 0.f);
        }
        // hi = bf16(v), lo = bf16(v - hi)
        float hx = __bfloat162float(__float2bfloat16(v.x));
        float hy = __bfloat162float(__float2bfloat16(v.y));
        float hz = __bfloat162float(__float2bfloat16(v.z));
        float hw_ = __bfloat162float(__float2bfloat16(v.w));
        uint32_t base = (uint32_t)(r * TSTRIDE + c4 * 4) * 2;
        *reinterpret_cast<uint32_t*>(smem + SM_AH + base)     = pack_bf16x2(v.x, v.y);
        *reinterpret_cast<uint32_t*>(smem + SM_AH + base + 4) = pack_bf16x2(v.z, v.w);
        *reinterpret_cast<uint32_t*>(smem + SM_AL + base)     = pack_bf16x2(v.x - hx, v.y - hy);
        *reinterpret_cast<uint32_t*>(smem + SM_AL + base + 4) = pack_bf16x2(v.z - hz, v.w - hw_);
    }
    // ---- load + convert + transpose W: Wt[n][k] ----
    #pragma unroll
    for (int it = 0; it < 16; it++) {
        int idx = tid + it * 256;          // 0..4095 float4s of W[k][n]
        int kr = idx >> 5;                 // k row 0..127
        int n4 = idx & 31;                 // float4 within row
        float4 v = *reinterpret_cast<const float4*>(&W[(size_t)kr * 128 + n4 * 4]);
        float h[4], l[4];
        h[0] = __bfloat162float(__float2bfloat16(v.x)); l[0] = v.x - h[0];
        h[1] = __bfloat162float(__float2bfloat16(v.y)); l[1] = v.y - h[1];
        h[2] = __bfloat162float(__float2bfloat16(v.z)); l[2] = v.z - h[2];
        h[3] = __bfloat162float(__float2bfloat16(v.w)); l[3] = v.w - h[3];
        float src[4] = {v.x, v.y, v.z, v.w};
        #pragma unroll
        for (int j = 0; j < 4; j++) {
            int n = n4 * 4 + j;
            uint32_t off = (uint32_t)(n * TSTRIDE + kr) * 2;
            *reinterpret_cast<__nv_bfloat16*>(smem + SM_WH + off) = __float2bfloat16(src[j]);
            *reinterpret_cast<__nv_bfloat16*>(smem + SM_WL + off) = __float2bfloat16(l[j]);
        }
    }
    __syncthreads();

    // ---- warp tiling: 8 warps in 4x2, each 32 rows x 64 cols ----
    int wrow = (wid >> 1) * 32;            // 0,32,64,96
    int wcol = (wid & 1) * 64;             // 0,64
    int fr   = lane >> 2;                  // fragment row 0..7
    int fc   = (lane & 3) * 2;             // fragment col pair base

    float acc[2][8][4];
    #pragma unroll
    for (int mi = 0; mi < 2; mi++)
        #pragma unroll
        for (int ni = 0; ni < 8; ni++)
            #pragma unroll
            for (int q = 0; q < 4; q++) acc[mi][ni][q] = 0.f;

    const int aoffs[3] = {SM_AH, SM_AH, SM_AL};
    const int woffs[3] = {SM_WH, SM_WL, SM_WH};

    #pragma unroll
    for (int t = 0; t < 3; t++) {
        const char* As = smem + aoffs[t];
        const char* Ws = smem + woffs[t];
        #pragma unroll
        for (int kk = 0; kk < 8; kk++) {
            int k0 = kk * 16;
            uint32_t a[2][4];
            #pragma unroll
            for (int mi = 0; mi < 2; mi++) {
                int r = wrow + mi * 16 + fr;
                uint32_t b0 = (uint32_t)(r * TSTRIDE + k0 + fc) * 2;
                uint32_t b8 = (uint32_t)((r + 8) * TSTRIDE + k0 + fc) * 2;
                a[mi][0] = *reinterpret_cast<const uint32_t*>(As + b0);
                a[mi][1] = *reinterpret_cast<const uint32_t*>(As + b8);
                a[mi][2] = *reinterpret_cast<const uint32_t*>(As + b0 + 16);
                a[mi][3] = *reinterpret_cast<const uint32_t*>(As + b8 + 16);
            }
            #pragma unroll
            for (int ni = 0; ni < 8; ni++) {
                int n = wcol + ni * 8 + fr;
                uint32_t bo = (uint32_t)(n * TSTRIDE + k0 + fc) * 2;
                uint32_t b0 = *reinterpret_cast<const uint32_t*>(Ws + bo);
                uint32_t b1 = *reinterpret_cast<const uint32_t*>(Ws + bo + 16);
                mma_bf16(acc[0][ni], a[0][0], a[0][1], a[0][2], a[0][3], b0, b1);
                mma_bf16(acc[1][ni], a[1][0], a[1][1], a[1][2], a[1][3], b0, b1);
            }
        }
    }

    // ---- epilogue: registers -> gmem ----
    #pragma unroll
    for (int mi = 0; mi < 2; mi++) {
        int r0 = m0 + wrow + mi * 16 + fr;
        #pragma unroll
        for (int ni = 0; ni < 8; ni++) {
            int c = wcol + ni * 8 + fc;
            if (r0 < M) {
                float2 v = make_float2(acc[mi][ni][0], acc[mi][ni][1]);
                *reinterpret_cast<float2*>(&out[(size_t)r0 * 128 + c]) = v;
            }
            if (r0 + 8 < M) {
                float2 v = make_float2(acc[mi][ni][2], acc[mi][ni][3]);
                *reinterpret_cast<float2*>(&out[(size_t)(r0 + 8) * 128 + c]) = v;
            }
        }
    }
}

// ---------------- degree / norm ----------------
__global__ void k_cnt_zero() {
    int n = blockIdx.x * blockDim.x + threadIdx.x;
    if (n < NN) g_cnt[n] = 0;
}
__global__ void k_cnt(const int* __restrict__ dst) {
    int e = blockIdx.x * blockDim.x + threadIdx.x;
    if (e < NE) atomicAdd(&g_cnt[dst[e]], 1);
}
__global__ void k_dinv() {
    int n = blockIdx.x * blockDim.x + threadIdx.x;
    if (n < NN) {
        float deg = (float)(g_cnt[n] + 1);
        g_dinv[n]  = rsqrtf(deg);
        g_dinv2[n] = 1.0f / deg;
    }
}

// ---------------- scan (CSR offsets) ----------------
__global__ __launch_bounds__(SCAN_B) void k_scan1() {
    __shared__ int s[SCAN_B];
    int t = threadIdx.x;
    int i = blockIdx.x * SCAN_B + t;
    int v = (i < NN) ? g_cnt[i] : 0;
    s[t] = v;
    __syncthreads();
    #pragma unroll
    for (int o = 1; o < SCAN_B; o <<= 1) {
        int x = (t >= o) ? s[t - o] : 0;
        __syncthreads();
        s[t] += x;
        __syncthreads();
    }
    if (i < NN) g_cnt[i] = s[t];
    if (t == SCAN_B - 1) g_bsum[blockIdx.x] = s[t];
}
__global__ void k_scan2() {
    if (threadIdx.x == 0) {
        int acc = 0;
        for (int b = 0; b < NSB; b++) { g_bpre[b] = acc; acc += g_bsum[b]; }
    }
}
__global__ __launch_bounds__(SCAN_B) void k_scan3() {
    int i = blockIdx.x * SCAN_B + threadIdx.x;
    if (i < NN) {
        int incl = g_cnt[i] + g_bpre[blockIdx.x];
        g_off[i + 1] = incl;
        if (i == 0) g_off[0] = 0;
    }
}
__global__ void k_cursor_init() {
    int n = blockIdx.x * blockDim.x + threadIdx.x;
    if (n < NN) g_cursor[n] = g_off[n];
}
__global__ void k_scatter(const int* __restrict__ src, const int* __restrict__ dst) {
    int e = blockIdx.x * blockDim.x + threadIdx.x;
    if (e < NE) {
        int s = src[e], t = dst[e];
        int p = atomicAdd(&g_cursor[t], 1);
        g_csrc[p] = s;
        g_cw[p]   = g_dinv[s] * g_dinv[t];
    }
}

// ---------------- CSR aggregation: one warp per node, no atomics ----------------
__global__ __launch_bounds__(256) void k_agg_csr(const float* __restrict__ hw,
                                                 float* __restrict__ agg)
{
    int gid  = blockIdx.x * blockDim.x + threadIdx.x;
    int n    = gid >> 5;
    int lane = threadIdx.x & 31;
    if (n >= NN) return;
    const float4* hw4 = reinterpret_cast<const float4*>(hw);
    float4 a = hw4[(size_t)n * 32 + lane];
    float s = g_dinv2[n];
    float4 acc = make_float4(a.x * s, a.y * s, a.z * s, a.w * s);
    int beg = g_off[n], end = g_off[n + 1];
    for (int i = beg; i < end; i++) {
        int   sn = g_csrc[i];
        float w  = g_cw[i];
        float4 v = __ldg(&hw4[(size_t)sn * 32 + lane]);
        acc.x = fmaf(w, v.x, acc.x);
        acc.y = fmaf(w, v.y, acc.y);
        acc.z = fmaf(w, v.z, acc.z);
        acc.w = fmaf(w, v.w, acc.w);
    }
    reinterpret_cast<float4*>(agg)[(size_t)n * 32 + lane] = acc;
}

// ---------------- pooling (batch is sorted) ----------------
__global__ void k_zero_pooled() {
    int i = blockIdx.x * blockDim.x + threadIdx.x;
    if (i < NG * DD) g_pooled[i] = 0.f;
}
__global__ void k_pool(const float* __restrict__ h,
                       const int* __restrict__ batch,
                       const float* __restrict__ bias)
{
    int d  = threadIdx.x;
    int n0 = blockIdx.x * 128;
    int n1 = n0 + 128; if (n1 > NN) n1 = NN;
    if (n0 >= NN) return;
    float b   = bias[d];
    float acc = 0.f;
    int gprev = batch[n0];
    for (int n = n0; n < n1; n++) {
        int g = batch[n];
        if (g != gprev) {
            atomicAdd(&g_pooled[gprev * 128 + d], acc);
            acc = 0.f;
            gprev = g;
        }
        acc += fmaxf(h[(size_t)n * 128 + d] + b, 0.f);
    }
    atomicAdd(&g_pooled[gprev * 128 + d], acc);
}

// ---------------- MLP head ----------------
__global__ void k_mlp(const float* __restrict__ in, const float* __restrict__ W,
                      const float* __restrict__ bias, float* __restrict__ out)
{
    __shared__ float row[128];
    int r = blockIdx.x, c = threadIdx.x;
    row[c] = in[r * 128 + c];
    __syncthreads();
    float acc = bias[c];
    #pragma unroll 8
    for (int k = 0; k < 128; k++)
        acc = fmaf(row[k], W[k * 128 + c], acc);
    out[r * 128 + c] = fmaxf(acc, 0.f);
}

__global__ void k_final(const float* __restrict__ z, const float* __restrict__ W3,
                        const float* __restrict__ b3, float* __restrict__ out)
{
    int g = blockIdx.x, t = threadIdx.x;
    float v = z[g * 128 + t] * W3[t];
    #pragma unroll
    for (int o = 16; o > 0; o >>= 1) v += __shfl_down_sync(0xffffffffu, v, o);
    __shared__ float partial[4];
    if ((t & 31) == 0) partial[t >> 5] = v;
    __syncthreads();
    if (t == 0) {
        float s = partial[0] + partial[1] + partial[2] + partial[3] + b3[0];
        out[g] = 1.f / (1.f + expf(-s));
    }
}

// ---------------- launch ----------------
extern "C" void kernel_launch(void* const* d_in, const int* in_sizes, int n_in,
                              void* d_out, int out_size)
{
    const float* x     = (const float*)d_in[0];
    const int*   ei    = (const int*)d_in[1];     // int32 (JAX x64 disabled)
    const int*   src   = ei;
    const int*   dst   = ei + NE;
    const int*   batch = (const int*)d_in[2];
    const float* convW = (const float*)d_in[3];
    const float* convB = (const float*)d_in[4];
    const float* W1    = (const float*)d_in[5];
    const float* b1    = (const float*)d_in[6];
    const float* W2    = (const float*)d_in[7];
    const float* b2    = (const float*)d_in[8];
    const float* W3    = (const float*)d_in[9];
    const float* b3    = (const float*)d_in[10];
    float* out = (float*)d_out;

    float *bufA, *bufB, *hw, *pooled, *z1, *z2;
    cudaGetSymbolAddress((void**)&bufA,   g_bufA);
    cudaGetSymbolAddress((void**)&bufB,   g_bufB);
    cudaGetSymbolAddress((void**)&hw,     g_hw);
    cudaGetSymbolAddress((void**)&pooled, g_pooled);
    cudaGetSymbolAddress((void**)&z1,     g_z1);
    cudaGetSymbolAddress((void**)&z2,     g_z2);

    static bool attr_done = false;
    if (!attr_done) {
        cudaFuncSetAttribute(k_gemm_mma, cudaFuncAttributeMaxDynamicSharedMemorySize, SMEM_MMA);
        attr_done = true;
    }

    // ---- CSR build (once per launch, reused by all 4 layers) ----
    k_cnt_zero   <<<(NN + 255) / 256, 256>>>();
    k_cnt        <<<(NE + 255) / 256, 256>>>(dst);
    k_dinv       <<<(NN + 255) / 256, 256>>>();
    k_scan1      <<<NSB, SCAN_B>>>();
    k_scan2      <<<1, 32>>>();
    k_scan3      <<<NSB, SCAN_B>>>();
    k_cursor_init<<<(NN + 255) / 256, 256>>>();
    k_scatter    <<<(NE + 255) / 256, 256>>>(src, dst);

    // ---- 4 GCN layers ----
    const float* hin = x;
    float* aggbuf[4] = {bufA, bufB, bufA, bufB};
    for (int l = 0; l < 4; l++) {
        const float* bias_prev = convB + (l > 0 ? (l - 1) * DD : 0);
        k_gemm_mma<<<NTILES, 256, SMEM_MMA>>>(hin, convW + (size_t)l * DD * DD,
                                              bias_prev, hw, NN, l > 0 ? 1 : 0);
        k_agg_csr<<<(NN * 32 + 255) / 256, 256>>>(hw, aggbuf[l]);
        hin = aggbuf[l];
    }

    // ---- pooling + MLP head ----
    k_zero_pooled<<<(NG * DD + 255) / 256, 256>>>();
    k_pool<<<(NN + 127) / 128, 128>>>(hin, batch, convB + 3 * DD);
    k_mlp<<<NG, 128>>>(pooled, W1, b1, z1);
    k_mlp<<<NG, 128>>>(z1, W2, b2, z2);
    k_final<<<NG, 128>>>(z2, W3, b3, out);
}

// round 6
// speedup vs baseline: 3.0151x; 1.5287x over previous
#include <cuda_runtime.h>
#include <cuda_bf16.h>
#include <math.h>
#include <cstdint>

#define NN   100000
#define NE   640000
#define DD   128
#define NG   512
#define SCAN_B 1024
#define NSB  ((NN + SCAN_B - 1) / SCAN_B)   // 98 scan blocks
#define NTILES ((NN + 127) / 128)           // 782
#define WSTRIDE 68                          // uint32 words per W-tile row (136 bf16)

// ---------------- scratch (no allocations allowed) ----------------
__device__ float g_bufA[(size_t)NN * DD];
__device__ float g_bufB[(size_t)NN * DD];
__device__ float g_hw  [(size_t)NN * DD];
__device__ float g_dinv[NN];
__device__ float g_dinv2[NN];
__device__ int   g_cnt [NN];
__device__ int   g_off [NN + 1];
__device__ int   g_cursor[NN];
__device__ int   g_csrc[NE];
__device__ float g_cw  [NE];
__device__ int   g_bsum[NSB];
__device__ int   g_bpre[NSB];
__device__ float g_pooled[NG * DD];
__device__ float g_z1[NG * DD];
__device__ float g_z2[NG * DD];
__device__ uint32_t g_wsplit[4 * 2 * 128 * WSTRIDE];   // [layer][hi/lo][n][kp]

// ---------------- smem layout for MMA GEMM (bytes) ----------------
#define WTILE_B (128 * WSTRIDE * 4)     // 34816 per (hi|lo)
#define SM_BIAS (2 * WTILE_B)           // 69632
#define SMEM_MMA (SM_BIAS + 512)        // 70144

__device__ __forceinline__ void mma_bf16(float c[4], uint32_t a0, uint32_t a1,
                                         uint32_t a2, uint32_t a3,
                                         uint32_t b0, uint32_t b1) {
    asm volatile(
        "mma.sync.aligned.m16n8k16.row.col.f32.bf16.bf16.f32 "
        "{%0,%1,%2,%3}, {%4,%5,%6,%7}, {%8,%9}, {%0,%1,%2,%3};"
        : "+f"(c[0]), "+f"(c[1]), "+f"(c[2]), "+f"(c[3])
        : "r"(a0), "r"(a1), "r"(a2), "r"(a3), "r"(b0), "r"(b1));
}

// ---------------- W split precompute: per layer, n-major hi/lo tiles ----------------
__global__ void k_wsplit(const float* __restrict__ convW) {
    int idx = blockIdx.x * 256 + threadIdx.x;     // 4*128*64 = 32768
    if (idx >= 4 * 128 * 64) return;
    int kp = idx & 63;
    int n  = (idx >> 6) & 127;
    int l  = idx >> 13;
    const float* Wl = convW + (size_t)l * 128 * 128;
    float w0 = Wl[(size_t)(2 * kp) * 128 + n];
    float w1 = Wl[(size_t)(2 * kp + 1) * 128 + n];
    __nv_bfloat162 h2 = __float22bfloat162_rn(make_float2(w0, w1));
    float2 hf = __bfloat1622float2(h2);
    __nv_bfloat162 l2 = __float22bfloat162_rn(make_float2(w0 - hf.x, w1 - hf.y));
    uint32_t* base = g_wsplit + (size_t)l * 2 * 128 * WSTRIDE;
    base[n * WSTRIDE + kp]                 = *reinterpret_cast<uint32_t*>(&h2);
    base[128 * WSTRIDE + n * WSTRIDE + kp] = *reinterpret_cast<uint32_t*>(&l2);
}

// ============ tensor-core GEMM: out[M,128] = act(A) @ W (3-term bf16 split) ============
__global__ __launch_bounds__(256, 2) void k_gemm_mma(
    const float* __restrict__ A, const uint32_t* __restrict__ wsp,
    const float* __restrict__ bias, float* __restrict__ out, int M, int fuse)
{
    extern __shared__ char smem[];
    int tid  = threadIdx.x;
    int wid  = tid >> 5;
    int lane = tid & 31;
    int m0   = blockIdx.x * 128;

    // ---- copy precomputed W hi/lo tiles (69632 B) + bias, conflict-free ----
    {
        const uint4* srcv = reinterpret_cast<const uint4*>(wsp);
        uint4* dstv = reinterpret_cast<uint4*>(smem);
        #pragma unroll
        for (int i = 0; i < 17; i++) dstv[tid + i * 256] = srcv[tid + i * 256];
        if (tid < 32)
            reinterpret_cast<float4*>(smem + SM_BIAS)[tid] =
                reinterpret_cast<const float4*>(bias)[tid];
    }
    __syncthreads();

    int fr   = lane >> 2;                  // 0..7
    int fc   = (lane & 3) * 2;             // 0,2,4,6
    int wrow = (wid >> 1) * 32;            // 0,32,64,96
    int wcol = (wid & 1) * 64;             // 0,64

    // row guards (4 row variants: mi*16 + dr*8)
    int  rr[4];
    bool ok[4];
    #pragma unroll
    for (int q = 0; q < 4; q++) {
        rr[q] = m0 + wrow + ((q >> 1) * 16 + (q & 1) * 8) + fr;
        ok[q] = rr[q] < M;
    }

    float acc[2][8][4];
    #pragma unroll
    for (int mi = 0; mi < 2; mi++)
        #pragma unroll
        for (int ni = 0; ni < 8; ni++)
            #pragma unroll
            for (int q = 0; q < 4; q++) acc[mi][ni][q] = 0.f;

    const float2*   A2  = reinterpret_cast<const float2*>(A);
    const float*    bsm = reinterpret_cast<const float*>(smem + SM_BIAS);
    const uint32_t* WH  = reinterpret_cast<const uint32_t*>(smem);
    const uint32_t* WL  = WH + 128 * WSTRIDE;

    #pragma unroll
    for (int kk = 0; kk < 8; kk++) {
        // bias pairs for this k-slab
        float bx0 = 0.f, by0 = 0.f, bx1 = 0.f, by1 = 0.f;
        if (fuse) {
            float2 t0 = *reinterpret_cast<const float2*>(bsm + kk * 16 + fc);
            float2 t1 = *reinterpret_cast<const float2*>(bsm + kk * 16 + fc + 8);
            bx0 = t0.x; by0 = t0.y; bx1 = t1.x; by1 = t1.y;
        }
        int kw = kk * 8 + (lane & 3);      // float2 index within a 128-col row

        // ---- A fragments straight from gmem, convert to hi/lo ----
        uint32_t ahi[2][4], alo[2][4];
        #pragma unroll
        for (int q = 0; q < 4; q++) {
            int mi = q >> 1, dr = q & 1;
            #pragma unroll
            for (int dk = 0; dk < 2; dk++) {
                float2 v = make_float2(0.f, 0.f);
                if (ok[q]) {
                    v = A2[(size_t)rr[q] * 64 + kw + dk * 4];
                    if (fuse) {
                        v.x = fmaxf(v.x + (dk ? bx1 : bx0), 0.f);
                        v.y = fmaxf(v.y + (dk ? by1 : by0), 0.f);
                    }
                }
                __nv_bfloat162 h2 = __float22bfloat162_rn(v);
                float2 hf = __bfloat1622float2(h2);
                __nv_bfloat162 l2 =
                    __float22bfloat162_rn(make_float2(v.x - hf.x, v.y - hf.y));
                int reg = dr + dk * 2;     // a0=(r,k) a1=(r+8,k) a2=(r,k+8) a3=(r+8,k+8)
                ahi[mi][reg] = *reinterpret_cast<uint32_t*>(&h2);
                alo[mi][reg] = *reinterpret_cast<uint32_t*>(&l2);
            }
        }

        // ---- B fragments from smem + 6 MMAs per ni ----
        int kb = kk * 8 + (lane & 3);      // word offset in W row
        #pragma unroll
        for (int ni = 0; ni < 8; ni++) {
            int n = wcol + ni * 8 + fr;
            uint32_t bh0 = WH[n * WSTRIDE + kb];
            uint32_t bh1 = WH[n * WSTRIDE + kb + 4];
            uint32_t bl0 = WL[n * WSTRIDE + kb];
            uint32_t bl1 = WL[n * WSTRIDE + kb + 4];
            #pragma unroll
            for (int mi = 0; mi < 2; mi++) {
                mma_bf16(acc[mi][ni], ahi[mi][0], ahi[mi][1], ahi[mi][2], ahi[mi][3], bh0, bh1);
                mma_bf16(acc[mi][ni], ahi[mi][0], ahi[mi][1], ahi[mi][2], ahi[mi][3], bl0, bl1);
                mma_bf16(acc[mi][ni], alo[mi][0], alo[mi][1], alo[mi][2], alo[mi][3], bh0, bh1);
            }
        }
    }

    // ---- epilogue: registers -> gmem ----
    #pragma unroll
    for (int mi = 0; mi < 2; mi++) {
        #pragma unroll
        for (int ni = 0; ni < 8; ni++) {
            int c = wcol + ni * 8 + fc;
            if (ok[mi * 2 + 0]) {
                float2 v = make_float2(acc[mi][ni][0], acc[mi][ni][1]);
                *reinterpret_cast<float2*>(&out[(size_t)rr[mi * 2 + 0] * 128 + c]) = v;
            }
            if (ok[mi * 2 + 1]) {
                float2 v = make_float2(acc[mi][ni][2], acc[mi][ni][3]);
                *reinterpret_cast<float2*>(&out[(size_t)rr[mi * 2 + 1] * 128 + c]) = v;
            }
        }
    }
}

// ---------------- degree / norm ----------------
__global__ void k_cnt_zero() {
    int n = blockIdx.x * blockDim.x + threadIdx.x;
    if (n < NN) g_cnt[n] = 0;
}
__global__ void k_cnt(const int* __restrict__ dst) {
    int e = blockIdx.x * blockDim.x + threadIdx.x;
    if (e < NE) atomicAdd(&g_cnt[dst[e]], 1);
}
__global__ void k_dinv() {
    int n = blockIdx.x * blockDim.x + threadIdx.x;
    if (n < NN) {
        float deg = (float)(g_cnt[n] + 1);
        g_dinv[n]  = rsqrtf(deg);
        g_dinv2[n] = 1.0f / deg;
    }
}

// ---------------- scan (CSR offsets) ----------------
__global__ __launch_bounds__(SCAN_B) void k_scan1() {
    __shared__ int s[SCAN_B];
    int t = threadIdx.x;
    int i = blockIdx.x * SCAN_B + t;
    int v = (i < NN) ? g_cnt[i] : 0;
    s[t] = v;
    __syncthreads();
    #pragma unroll
    for (int o = 1; o < SCAN_B; o <<= 1) {
        int x = (t >= o) ? s[t - o] : 0;
        __syncthreads();
        s[t] += x;
        __syncthreads();
    }
    if (i < NN) g_cnt[i] = s[t];
    if (t == SCAN_B - 1) g_bsum[blockIdx.x] = s[t];
}
__global__ void k_scan2() {
    if (threadIdx.x == 0) {
        int acc = 0;
        for (int b = 0; b < NSB; b++) { g_bpre[b] = acc; acc += g_bsum[b]; }
    }
}
__global__ __launch_bounds__(SCAN_B) void k_scan3() {
    int i = blockIdx.x * SCAN_B + threadIdx.x;
    if (i < NN) {
        int incl = g_cnt[i] + g_bpre[blockIdx.x];
        g_off[i + 1] = incl;
        if (i == 0) g_off[0] = 0;
    }
}
__global__ void k_cursor_init() {
    int n = blockIdx.x * blockDim.x + threadIdx.x;
    if (n < NN) g_cursor[n] = g_off[n];
}
__global__ void k_scatter(const int* __restrict__ src, const int* __restrict__ dst) {
    int e = blockIdx.x * blockDim.x + threadIdx.x;
    if (e < NE) {
        int s = src[e], t = dst[e];
        int p = atomicAdd(&g_cursor[t], 1);
        g_csrc[p] = s;
        g_cw[p]   = g_dinv[s] * g_dinv[t];
    }
}

// ---------------- CSR aggregation: one warp per node, no atomics ----------------
__global__ __launch_bounds__(256) void k_agg_csr(const float* __restrict__ hw,
                                                 float* __restrict__ agg)
{
    int gid  = blockIdx.x * blockDim.x + threadIdx.x;
    int n    = gid >> 5;
    int lane = threadIdx.x & 31;
    if (n >= NN) return;
    const float4* hw4 = reinterpret_cast<const float4*>(hw);
    float4 a = hw4[(size_t)n * 32 + lane];
    float s = g_dinv2[n];
    float4 acc = make_float4(a.x * s, a.y * s, a.z * s, a.w * s);
    int beg = g_off[n], end = g_off[n + 1];
    for (int i = beg; i < end; i++) {
        int   sn = g_csrc[i];
        float w  = g_cw[i];
        float4 v = __ldg(&hw4[(size_t)sn * 32 + lane]);
        acc.x = fmaf(w, v.x, acc.x);
        acc.y = fmaf(w, v.y, acc.y);
        acc.z = fmaf(w, v.z, acc.z);
        acc.w = fmaf(w, v.w, acc.w);
    }
    reinterpret_cast<float4*>(agg)[(size_t)n * 32 + lane] = acc;
}

// ---------------- pooling (batch is sorted) ----------------
__global__ void k_zero_pooled() {
    int i = blockIdx.x * blockDim.x + threadIdx.x;
    if (i < NG * DD) g_pooled[i] = 0.f;
}
__global__ void k_pool(const float* __restrict__ h,
                       const int* __restrict__ batch,
                       const float* __restrict__ bias)
{
    int d  = threadIdx.x;
    int n0 = blockIdx.x * 128;
    int n1 = n0 + 128; if (n1 > NN) n1 = NN;
    if (n0 >= NN) return;
    float b   = bias[d];
    float acc = 0.f;
    int gprev = batch[n0];
    for (int n = n0; n < n1; n++) {
        int g = batch[n];
        if (g != gprev) {
            atomicAdd(&g_pooled[gprev * 128 + d], acc);
            acc = 0.f;
            gprev = g;
        }
        acc += fmaxf(h[(size_t)n * 128 + d] + b, 0.f);
    }
    atomicAdd(&g_pooled[gprev * 128 + d], acc);
}

// ---------------- MLP head ----------------
__global__ void k_mlp(const float* __restrict__ in, const float* __restrict__ W,
                      const float* __restrict__ bias, float* __restrict__ out)
{
    __shared__ float row[128];
    int r = blockIdx.x, c = threadIdx.x;
    row[c] = in[r * 128 + c];
    __syncthreads();
    float acc = bias[c];
    #pragma unroll 8
    for (int k = 0; k < 128; k++)
        acc = fmaf(row[k], W[k * 128 + c], acc);
    out[r * 128 + c] = fmaxf(acc, 0.f);
}

__global__ void k_final(const float* __restrict__ z, const float* __restrict__ W3,
                        const float* __restrict__ b3, float* __restrict__ out)
{
    int g = blockIdx.x, t = threadIdx.x;
    float v = z[g * 128 + t] * W3[t];
    #pragma unroll
    for (int o = 16; o > 0; o >>= 1) v += __shfl_down_sync(0xffffffffu, v, o);
    __shared__ float partial[4];
    if ((t & 31) == 0) partial[t >> 5] = v;
    __syncthreads();
    if (t == 0) {
        float s = partial[0] + partial[1] + partial[2] + partial[3] + b3[0];
        out[g] = 1.f / (1.f + expf(-s));
    }
}

// ---------------- launch ----------------
extern "C" void kernel_launch(void* const* d_in, const int* in_sizes, int n_in,
                              void* d_out, int out_size)
{
    const float* x     = (const float*)d_in[0];
    const int*   ei    = (const int*)d_in[1];     // int32 (JAX x64 disabled)
    const int*   src   = ei;
    const int*   dst   = ei + NE;
    const int*   batch = (const int*)d_in[2];
    const float* convW = (const float*)d_in[3];
    const float* convB = (const float*)d_in[4];
    const float* W1    = (const float*)d_in[5];
    const float* b1    = (const float*)d_in[6];
    const float* W2    = (const float*)d_in[7];
    const float* b2    = (const float*)d_in[8];
    const float* W3    = (const float*)d_in[9];
    const float* b3    = (const float*)d_in[10];
    float* out = (float*)d_out;

    float *bufA, *bufB, *hw, *pooled, *z1, *z2;
    uint32_t* wsp;
    cudaGetSymbolAddress((void**)&bufA,   g_bufA);
    cudaGetSymbolAddress((void**)&bufB,   g_bufB);
    cudaGetSymbolAddress((void**)&hw,     g_hw);
    cudaGetSymbolAddress((void**)&pooled, g_pooled);
    cudaGetSymbolAddress((void**)&z1,     g_z1);
    cudaGetSymbolAddress((void**)&z2,     g_z2);
    cudaGetSymbolAddress((void**)&wsp,    g_wsplit);

    static bool attr_done = false;
    if (!attr_done) {
        cudaFuncSetAttribute(k_gemm_mma, cudaFuncAttributeMaxDynamicSharedMemorySize, SMEM_MMA);
        attr_done = true;
    }

    // ---- CSR build + W split (once per launch) ----
    k_cnt_zero   <<<(NN + 255) / 256, 256>>>();
    k_cnt        <<<(NE + 255) / 256, 256>>>(dst);
    k_dinv       <<<(NN + 255) / 256, 256>>>();
    k_scan1      <<<NSB, SCAN_B>>>();
    k_scan2      <<<1, 32>>>();
    k_scan3      <<<NSB, SCAN_B>>>();
    k_cursor_init<<<(NN + 255) / 256, 256>>>();
    k_scatter    <<<(NE + 255) / 256, 256>>>(src, dst);
    k_wsplit     <<<128, 256>>>(convW);

    // ---- 4 GCN layers ----
    const float* hin = x;
    float* aggbuf[4] = {bufA, bufB, bufA, bufB};
    for (int l = 0; l < 4; l++) {
        const float* bias_prev = convB + (l > 0 ? (l - 1) * DD : 0);
        k_gemm_mma<<<NTILES, 256, SMEM_MMA>>>(hin, wsp + (size_t)l * 2 * 128 * WSTRIDE,
                                              bias_prev, hw, NN, l > 0 ? 1 : 0);
        k_agg_csr<<<(NN * 32 + 255) / 256, 256>>>(hw, aggbuf[l]);
        hin = aggbuf[l];
    }

    // ---- pooling + MLP head ----
    k_zero_pooled<<<(NG * DD + 255) / 256, 256>>>();
    k_pool<<<(NN + 127) / 128, 128>>>(hin, batch, convB + 3 * DD);
    k_mlp<<<NG, 128>>>(pooled, W1, b1, z1);
    k_mlp<<<NG, 128>>>(z1, W2, b2, z2);
    k_final<<<NG, 128>>>(z2, W3, b3, out);
}

// round 7
// speedup vs baseline: 3.1744x; 1.0528x over previous
#include <cuda_runtime.h>
#include <cuda_bf16.h>
#include <math.h>
#include <cstdint>

#define NN   100000
#define NE   640000
#define DD   128
#define NG   512
#define SCAN_B 1024
#define NSB  ((NN + SCAN_B - 1) / SCAN_B)   // 98 scan blocks
#define NTILES ((NN + 127) / 128)           // 782

// ---------------- scratch (no allocations allowed) ----------------
__device__ float g_bufA[(size_t)NN * DD];
__device__ float g_bufB[(size_t)NN * DD];
__device__ float g_hw  [(size_t)NN * DD];
__device__ float g_dinv[NN];
__device__ float g_dinv2[NN];
__device__ int   g_cnt [NN];
__device__ int   g_off [NN + 1];
__device__ int   g_cursor[NN];
__device__ int   g_csrc[NE];
__device__ float g_cw  [NE];
__device__ int   g_bsum[NSB];
__device__ int   g_bpre[NSB];
__device__ float g_pooled[NG * DD];
__device__ float g_z1[NG * DD];
__device__ float g_z2[NG * DD];
// packed W fragments: [layer][n(128)][kk(8)][q(4)] uint4 = {hi@kb, hi@kb+4, lo@kb, lo@kb+4}
__device__ uint4 g_wpack[4 * 128 * 8 * 4];

// ---------------- smem layout for MMA GEMM ----------------
#define WPAD 36                          // uint4 per n-row in smem (padded from 32)
#define SM_W_BYTES (128 * WPAD * 16)     // 73728
#define SMEM_MMA (SM_W_BYTES + 512)      // + bias

__device__ __forceinline__ void mma_bf16(float c[4], uint32_t a0, uint32_t a1,
                                         uint32_t a2, uint32_t a3,
                                         uint32_t b0, uint32_t b1) {
    asm volatile(
        "mma.sync.aligned.m16n8k16.row.col.f32.bf16.bf16.f32 "
        "{%0,%1,%2,%3}, {%4,%5,%6,%7}, {%8,%9}, {%0,%1,%2,%3};"
        : "+f"(c[0]), "+f"(c[1]), "+f"(c[2]), "+f"(c[3])
        : "r"(a0), "r"(a1), "r"(a2), "r"(a3), "r"(b0), "r"(b1));
}

__device__ __forceinline__ uint32_t bf2_of(float a, float b) {
    __nv_bfloat162 t = __float22bfloat162_rn(make_float2(a, b));
    return *reinterpret_cast<uint32_t*>(&t);
}

// ---------------- W pack precompute ----------------
__global__ void k_wsplit(const float* __restrict__ convW) {
    int idx = blockIdx.x * 256 + threadIdx.x;     // 4*128*8*4 = 16384
    if (idx >= 16384) return;
    int q  = idx & 3;
    int kk = (idx >> 2) & 7;
    int n  = (idx >> 5) & 127;
    int l  = idx >> 12;
    int k0 = kk * 16 + q * 2;
    const float* Wl = convW + (size_t)l * 16384;
    float w00 = Wl[(size_t)(k0    ) * 128 + n], w01 = Wl[(size_t)(k0 + 1) * 128 + n];
    float w10 = Wl[(size_t)(k0 + 8) * 128 + n], w11 = Wl[(size_t)(k0 + 9) * 128 + n];
    __nv_bfloat162 h0 = __float22bfloat162_rn(make_float2(w00, w01));
    __nv_bfloat162 h1 = __float22bfloat162_rn(make_float2(w10, w11));
    float2 f0 = __bfloat1622float2(h0), f1 = __bfloat1622float2(h1);
    uint4 v;
    v.x = *reinterpret_cast<uint32_t*>(&h0);
    v.y = *reinterpret_cast<uint32_t*>(&h1);
    v.z = bf2_of(w00 - f0.x, w01 - f0.y);
    v.w = bf2_of(w10 - f1.x, w11 - f1.y);
    g_wpack[idx] = v;
}

// ============ tensor-core GEMM: out[M,128] = act(A) @ W (3-term bf16 split) ============
__global__ __launch_bounds__(256, 2) void k_gemm_mma(
    const float* __restrict__ A, const uint4* __restrict__ wp,
    const float* __restrict__ bias, float* __restrict__ out, int M, int fuse)
{
    extern __shared__ char smem[];
    uint4* Wp = reinterpret_cast<uint4*>(smem);
    float* bsm = reinterpret_cast<float*>(smem + SM_W_BYTES);
    int tid  = threadIdx.x;
    int wid  = tid >> 5;
    int lane = tid & 31;
    int m0   = blockIdx.x * 128;

    // ---- stage packed W (4096 uint4) into padded smem + bias ----
    #pragma unroll
    for (int i = 0; i < 16; i++) {
        int idx = tid + i * 256;           // [n][kk][q], 32 uint4 per n
        int n = idx >> 5, r = idx & 31;
        Wp[n * WPAD + r] = wp[idx];
    }
    if (tid < 32)
        reinterpret_cast<float4*>(bsm)[tid] = reinterpret_cast<const float4*>(bias)[tid];
    __syncthreads();

    int fr = lane >> 2;                    // 0..7
    int q  = lane & 3;                     // 0..3
    int fc = q * 2;
    int r0 = m0 + wid * 16 + fr;
    int r1 = r0 + 8;
    bool ok0 = r0 < M, ok1 = r1 < M;

    float acc[16][4];
    #pragma unroll
    for (int ni = 0; ni < 16; ni++)
        #pragma unroll
        for (int p = 0; p < 4; p++) acc[ni][p] = 0.f;

    const float2* A2 = reinterpret_cast<const float2*>(A);

    #pragma unroll
    for (int kk = 0; kk < 8; kk++) {
        int kw = kk * 8 + q;               // float2 index within 128-col row
        float bx0 = 0.f, by0 = 0.f, bx1 = 0.f, by1 = 0.f;
        if (fuse) {
            float2 t0 = *reinterpret_cast<const float2*>(bsm + kk * 16 + fc);
            float2 t1 = *reinterpret_cast<const float2*>(bsm + kk * 16 + fc + 8);
            bx0 = t0.x; by0 = t0.y; bx1 = t1.x; by1 = t1.y;
        }
        float2 v00 = make_float2(0.f, 0.f), v01 = v00, v10 = v00, v11 = v00;
        if (ok0) { v00 = A2[(size_t)r0 * 64 + kw]; v01 = A2[(size_t)r0 * 64 + kw + 4]; }
        if (ok1) { v10 = A2[(size_t)r1 * 64 + kw]; v11 = A2[(size_t)r1 * 64 + kw + 4]; }
        if (fuse) {
            v00.x = fmaxf(v00.x + bx0, 0.f); v00.y = fmaxf(v00.y + by0, 0.f);
            v10.x = fmaxf(v10.x + bx0, 0.f); v10.y = fmaxf(v10.y + by0, 0.f);
            v01.x = fmaxf(v01.x + bx1, 0.f); v01.y = fmaxf(v01.y + by1, 0.f);
            v11.x = fmaxf(v11.x + bx1, 0.f); v11.y = fmaxf(v11.y + by1, 0.f);
        }
        // A fragments: a0=(r0,k) a1=(r1,k) a2=(r0,k+8) a3=(r1,k+8); hi + lo
        uint32_t ah[4], al[4];
        {
            __nv_bfloat162 h;
            float2 f;
            h = __float22bfloat162_rn(v00); f = __bfloat1622float2(h);
            ah[0] = *reinterpret_cast<uint32_t*>(&h); al[0] = bf2_of(v00.x - f.x, v00.y - f.y);
            h = __float22bfloat162_rn(v10); f = __bfloat1622float2(h);
            ah[1] = *reinterpret_cast<uint32_t*>(&h); al[1] = bf2_of(v10.x - f.x, v10.y - f.y);
            h = __float22bfloat162_rn(v01); f = __bfloat1622float2(h);
            ah[2] = *reinterpret_cast<uint32_t*>(&h); al[2] = bf2_of(v01.x - f.x, v01.y - f.y);
            h = __float22bfloat162_rn(v11); f = __bfloat1622float2(h);
            ah[3] = *reinterpret_cast<uint32_t*>(&h); al[3] = bf2_of(v11.x - f.x, v11.y - f.y);
        }
        #pragma unroll
        for (int ni = 0; ni < 16; ni++) {
            int n = ni * 8 + fr;
            uint4 b = Wp[n * WPAD + kk * 4 + q];
            mma_bf16(acc[ni], ah[0], ah[1], ah[2], ah[3], b.x, b.y);  // hi*W_hi
            mma_bf16(acc[ni], ah[0], ah[1], ah[2], ah[3], b.z, b.w);  // hi*W_lo
            mma_bf16(acc[ni], al[0], al[1], al[2], al[3], b.x, b.y);  // lo*W_hi
        }
    }

    // ---- epilogue ----
    #pragma unroll
    for (int ni = 0; ni < 16; ni++) {
        int c = ni * 8 + fc;
        if (ok0) {
            float2 v = make_float2(acc[ni][0], acc[ni][1]);
            *reinterpret_cast<float2*>(&out[(size_t)r0 * 128 + c]) = v;
        }
        if (ok1) {
            float2 v = make_float2(acc[ni][2], acc[ni][3]);
            *reinterpret_cast<float2*>(&out[(size_t)r1 * 128 + c]) = v;
        }
    }
}

// ---------------- degree / norm ----------------
__global__ void k_cnt_zero() {
    int n = blockIdx.x * blockDim.x + threadIdx.x;
    if (n < NN) g_cnt[n] = 0;
}
__global__ void k_cnt(const int* __restrict__ dst) {
    int e = blockIdx.x * blockDim.x + threadIdx.x;
    if (e < NE) atomicAdd(&g_cnt[dst[e]], 1);
}
__global__ void k_dinv() {
    int n = blockIdx.x * blockDim.x + threadIdx.x;
    if (n < NN) {
        float deg = (float)(g_cnt[n] + 1);
        g_dinv[n]  = rsqrtf(deg);
        g_dinv2[n] = 1.0f / deg;
    }
}

// ---------------- scan (CSR offsets) ----------------
__global__ __launch_bounds__(SCAN_B) void k_scan1() {
    __shared__ int s[SCAN_B];
    int t = threadIdx.x;
    int i = blockIdx.x * SCAN_B + t;
    int v = (i < NN) ? g_cnt[i] : 0;
    s[t] = v;
    __syncthreads();
    #pragma unroll
    for (int o = 1; o < SCAN_B; o <<= 1) {
        int x = (t >= o) ? s[t - o] : 0;
        __syncthreads();
        s[t] += x;
        __syncthreads();
    }
    if (i < NN) g_cnt[i] = s[t];
    if (t == SCAN_B - 1) g_bsum[blockIdx.x] = s[t];
}
__global__ void k_scan2() {
    if (threadIdx.x == 0) {
        int acc = 0;
        for (int b = 0; b < NSB; b++) { g_bpre[b] = acc; acc += g_bsum[b]; }
    }
}
__global__ __launch_bounds__(SCAN_B) void k_scan3() {
    int i = blockIdx.x * SCAN_B + threadIdx.x;
    if (i < NN) {
        int incl = g_cnt[i] + g_bpre[blockIdx.x];
        g_off[i + 1] = incl;
        if (i == 0) g_off[0] = 0;
    }
}
__global__ void k_cursor_init() {
    int n = blockIdx.x * blockDim.x + threadIdx.x;
    if (n < NN) g_cursor[n] = g_off[n];
}
__global__ void k_scatter(const int* __restrict__ src, const int* __restrict__ dst) {
    int e = blockIdx.x * blockDim.x + threadIdx.x;
    if (e < NE) {
        int s = src[e], t = dst[e];
        int p = atomicAdd(&g_cursor[t], 1);
        g_csrc[p] = s;
        g_cw[p]   = g_dinv[s] * g_dinv[t];
    }
}

// ---------------- CSR aggregation: one warp per node, no atomics ----------------
__global__ __launch_bounds__(256) void k_agg_csr(const float* __restrict__ hw,
                                                 float* __restrict__ agg)
{
    int gid  = blockIdx.x * blockDim.x + threadIdx.x;
    int n    = gid >> 5;
    int lane = threadIdx.x & 31;
    if (n >= NN) return;
    const float4* hw4 = reinterpret_cast<const float4*>(hw);
    float4 a = hw4[(size_t)n * 32 + lane];
    float s = g_dinv2[n];
    float4 acc = make_float4(a.x * s, a.y * s, a.z * s, a.w * s);
    int beg = g_off[n], end = g_off[n + 1];
    for (int i = beg; i < end; i++) {
        int   sn = g_csrc[i];
        float w  = g_cw[i];
        float4 v = __ldg(&hw4[(size_t)sn * 32 + lane]);
        acc.x = fmaf(w, v.x, acc.x);
        acc.y = fmaf(w, v.y, acc.y);
        acc.z = fmaf(w, v.z, acc.z);
        acc.w = fmaf(w, v.w, acc.w);
    }
    reinterpret_cast<float4*>(agg)[(size_t)n * 32 + lane] = acc;
}

// ---------------- pooling (batch is sorted) ----------------
__global__ void k_zero_pooled() {
    int i = blockIdx.x * blockDim.x + threadIdx.x;
    if (i < NG * DD) g_pooled[i] = 0.f;
}
__global__ void k_pool(const float* __restrict__ h,
                       const int* __restrict__ batch,
                       const float* __restrict__ bias)
{
    int d  = threadIdx.x;
    int n0 = blockIdx.x * 128;
    int n1 = n0 + 128; if (n1 > NN) n1 = NN;
    if (n0 >= NN) return;
    float b   = bias[d];
    float acc = 0.f;
    int gprev = batch[n0];
    for (int n = n0; n < n1; n++) {
        int g = batch[n];
        if (g != gprev) {
            atomicAdd(&g_pooled[gprev * 128 + d], acc);
            acc = 0.f;
            gprev = g;
        }
        acc += fmaxf(h[(size_t)n * 128 + d] + b, 0.f);
    }
    atomicAdd(&g_pooled[gprev * 128 + d], acc);
}

// ---------------- MLP head ----------------
__global__ void k_mlp(const float* __restrict__ in, const float* __restrict__ W,
                      const float* __restrict__ bias, float* __restrict__ out)
{
    __shared__ float row[128];
    int r = blockIdx.x, c = threadIdx.x;
    row[c] = in[r * 128 + c];
    __syncthreads();
    float acc = bias[c];
    #pragma unroll 8
    for (int k = 0; k < 128; k++)
        acc = fmaf(row[k], W[k * 128 + c], acc);
    out[r * 128 + c] = fmaxf(acc, 0.f);
}

__global__ void k_final(const float* __restrict__ z, const float* __restrict__ W3,
                        const float* __restrict__ b3, float* __restrict__ out)
{
    int g = blockIdx.x, t = threadIdx.x;
    float v = z[g * 128 + t] * W3[t];
    #pragma unroll
    for (int o = 16; o > 0; o >>= 1) v += __shfl_down_sync(0xffffffffu, v, o);
    __shared__ float partial[4];
    if ((t & 31) == 0) partial[t >> 5] = v;
    __syncthreads();
    if (t == 0) {
        float s = partial[0] + partial[1] + partial[2] + partial[3] + b3[0];
        out[g] = 1.f / (1.f + expf(-s));
    }
}

// ---------------- launch ----------------
extern "C" void kernel_launch(void* const* d_in, const int* in_sizes, int n_in,
                              void* d_out, int out_size)
{
    const float* x     = (const float*)d_in[0];
    const int*   ei    = (const int*)d_in[1];     // int32 (JAX x64 disabled)
    const int*   src   = ei;
    const int*   dst   = ei + NE;
    const int*   batch = (const int*)d_in[2];
    const float* convW = (const float*)d_in[3];
    const float* convB = (const float*)d_in[4];
    const float* W1    = (const float*)d_in[5];
    const float* b1    = (const float*)d_in[6];
    const float* W2    = (const float*)d_in[7];
    const float* b2    = (const float*)d_in[8];
    const float* W3    = (const float*)d_in[9];
    const float* b3    = (const float*)d_in[10];
    float* out = (float*)d_out;

    float *bufA, *bufB, *hw, *pooled, *z1, *z2;
    uint4* wpk;
    cudaGetSymbolAddress((void**)&bufA,   g_bufA);
    cudaGetSymbolAddress((void**)&bufB,   g_bufB);
    cudaGetSymbolAddress((void**)&hw,     g_hw);
    cudaGetSymbolAddress((void**)&pooled, g_pooled);
    cudaGetSymbolAddress((void**)&z1,     g_z1);
    cudaGetSymbolAddress((void**)&z2,     g_z2);
    cudaGetSymbolAddress((void**)&wpk,    g_wpack);

    static bool attr_done = false;
    if (!attr_done) {
        cudaFuncSetAttribute(k_gemm_mma, cudaFuncAttributeMaxDynamicSharedMemorySize, SMEM_MMA);
        attr_done = true;
    }

    // ---- CSR build + W pack (once per launch) ----
    k_cnt_zero   <<<(NN + 255) / 256, 256>>>();
    k_cnt        <<<(NE + 255) / 256, 256>>>(dst);
    k_dinv       <<<(NN + 255) / 256, 256>>>();
    k_scan1      <<<NSB, SCAN_B>>>();
    k_scan2      <<<1, 32>>>();
    k_scan3      <<<NSB, SCAN_B>>>();
    k_cursor_init<<<(NN + 255) / 256, 256>>>();
    k_scatter    <<<(NE + 255) / 256, 256>>>(src, dst);
    k_wsplit     <<<64, 256>>>(convW);

    // ---- 4 GCN layers ----
    const float* hin = x;
    float* aggbuf[4] = {bufA, bufB, bufA, bufB};
    for (int l = 0; l < 4; l++) {
        const float* bias_prev = convB + (l > 0 ? (l - 1) * DD : 0);
        k_gemm_mma<<<NTILES, 256, SMEM_MMA>>>(hin, wpk + (size_t)l * 4096,
                                              bias_prev, hw, NN, l > 0 ? 1 : 0);
        k_agg_csr<<<(NN * 32 + 255) / 256, 256>>>(hw, aggbuf[l]);
        hin = aggbuf[l];
    }

    // ---- pooling + MLP head ----
    k_zero_pooled<<<(NG * DD + 255) / 256, 256>>>();
    k_pool<<<(NN + 127) / 128, 128>>>(hin, batch, convB + 3 * DD);
    k_mlp<<<NG, 128>>>(pooled, W1, b1, z1);
    k_mlp<<<NG, 128>>>(z1, W2, b2, z2);
    k_final<<<NG, 128>>>(z2, W3, b3, out);
}

// round 8
// speedup vs baseline: 3.3989x; 1.0707x over previous
#include <cuda_runtime.h>
#include <cuda_bf16.h>
#include <math.h>
#include <cstdint>

#define NN   100000
#define NE   640000
#define DD   128
#define NG   512
#define SCAN_B 1024
#define NSB  ((NN + SCAN_B - 1) / SCAN_B)   // 98 scan blocks
#define NTILES ((NN + 127) / 128)           // 782

// ---------------- scratch (no allocations allowed) ----------------
__device__ uint2 g_hwb  [(size_t)NN * 32];   // hw in bf16x2: 64 uint32 per row (25.6MB)
__device__ uint4 g_hpack[(size_t)NN * 32];   // relu(agg+b) as hi|lo packed uint32 per feat
__device__ float g_dinv[NN];
__device__ float g_dinv2[NN];
__device__ int   g_cnt [NN];
__device__ int   g_off [NN + 1];
__device__ int   g_cursor[NN];
__device__ int   g_csrc[NE];
__device__ float g_cw  [NE];
__device__ int   g_bsum[NSB];
__device__ int   g_bpre[NSB];
__device__ float g_pooled[NG * DD];
__device__ float g_z1[NG * DD];
__device__ float g_z2[NG * DD];
// packed W fragments: [layer][n(128)][kk(8)][q(4)] uint4 = {hi@kb, hi@kb+4, lo@kb, lo@kb+4}
__device__ uint4 g_wpack[4 * 128 * 8 * 4];

// ---------------- smem layout for MMA GEMM ----------------
#define WPAD 36                          // uint4 per n-row in smem (padded from 32)
#define SMEM_MMA (128 * WPAD * 16)       // 73728

__device__ __forceinline__ void mma_bf16(float c[4], uint32_t a0, uint32_t a1,
                                         uint32_t a2, uint32_t a3,
                                         uint32_t b0, uint32_t b1) {
    asm volatile(
        "mma.sync.aligned.m16n8k16.row.col.f32.bf16.bf16.f32 "
        "{%0,%1,%2,%3}, {%4,%5,%6,%7}, {%8,%9}, {%0,%1,%2,%3};"
        : "+f"(c[0]), "+f"(c[1]), "+f"(c[2]), "+f"(c[3])
        : "r"(a0), "r"(a1), "r"(a2), "r"(a3), "r"(b0), "r"(b1));
}

__device__ __forceinline__ uint32_t bf2_of(float a, float b) {
    __nv_bfloat162 t = __float22bfloat162_rn(make_float2(a, b));
    return *reinterpret_cast<uint32_t*>(&t);
}
__device__ __forceinline__ float2 bf2f(uint32_t u) {
    __nv_bfloat162 h = *reinterpret_cast<__nv_bfloat162*>(&u);
    return __bfloat1622float2(h);
}
// pack value as bf16 hi (low16) | bf16 lo (high16)
__device__ __forceinline__ uint32_t packsplit(float v) {
    __nv_bfloat16 h = __float2bfloat16(v);
    float hf = __bfloat162float(h);
    __nv_bfloat16 l = __float2bfloat16(v - hf);
    uint16_t hu = *reinterpret_cast<uint16_t*>(&h);
    uint16_t lu = *reinterpret_cast<uint16_t*>(&l);
    return (uint32_t)hu | ((uint32_t)lu << 16);
}

// ---------------- init: zero cnt + zero pooled + W pack (one kernel) ----------------
__global__ void k_init(const float* __restrict__ convW) {
    int idx = blockIdx.x * 256 + threadIdx.x;
    if (idx < NN) g_cnt[idx] = 0;
    if (idx < NG * DD) g_pooled[idx] = 0.f;
    if (idx < 16384) {   // 4*128*8*4 W fragments
        int q  = idx & 3;
        int kk = (idx >> 2) & 7;
        int n  = (idx >> 5) & 127;
        int l  = idx >> 12;
        int k0 = kk * 16 + q * 2;
        const float* Wl = convW + (size_t)l * 16384;
        float w00 = Wl[(size_t)(k0    ) * 128 + n], w01 = Wl[(size_t)(k0 + 1) * 128 + n];
        float w10 = Wl[(size_t)(k0 + 8) * 128 + n], w11 = Wl[(size_t)(k0 + 9) * 128 + n];
        __nv_bfloat162 h0 = __float22bfloat162_rn(make_float2(w00, w01));
        __nv_bfloat162 h1 = __float22bfloat162_rn(make_float2(w10, w11));
        float2 f0 = __bfloat1622float2(h0), f1 = __bfloat1622float2(h1);
        uint4 v;
        v.x = *reinterpret_cast<uint32_t*>(&h0);
        v.y = *reinterpret_cast<uint32_t*>(&h1);
        v.z = bf2_of(w00 - f0.x, w01 - f0.y);
        v.w = bf2_of(w10 - f1.x, w11 - f1.y);
        g_wpack[idx] = v;
    }
}

__global__ void k_cnt(const int* __restrict__ dst) {
    int e = blockIdx.x * blockDim.x + threadIdx.x;
    if (e < NE) atomicAdd(&g_cnt[dst[e]], 1);
}

// ---------------- scan (CSR offsets); dinv fused ----------------
__global__ __launch_bounds__(SCAN_B) void k_scan1() {
    __shared__ int s[SCAN_B];
    int t = threadIdx.x;
    int i = blockIdx.x * SCAN_B + t;
    int v = (i < NN) ? g_cnt[i] : 0;
    if (i < NN) {
        float deg = (float)(v + 1);
        g_dinv[i]  = rsqrtf(deg);
        g_dinv2[i] = 1.0f / deg;
    }
    s[t] = v;
    __syncthreads();
    #pragma unroll
    for (int o = 1; o < SCAN_B; o <<= 1) {
        int x = (t >= o) ? s[t - o] : 0;
        __syncthreads();
        s[t] += x;
        __syncthreads();
    }
    if (i < NN) g_cnt[i] = s[t];
    if (t == SCAN_B - 1) g_bsum[blockIdx.x] = s[t];
}
__global__ void k_scan2() {
    __shared__ int s[128];
    int t = threadIdx.x;
    int v = (t < NSB) ? g_bsum[t] : 0;
    s[t] = v;
    __syncthreads();
    #pragma unroll
    for (int o = 1; o < 128; o <<= 1) {
        int x = (t >= o) ? s[t - o] : 0;
        __syncthreads();
        s[t] += x;
        __syncthreads();
    }
    if (t < NSB) g_bpre[t] = s[t] - v;   // exclusive
}
__global__ __launch_bounds__(SCAN_B) void k_scan3() {
    int i = blockIdx.x * SCAN_B + threadIdx.x;
    if (i < NN) {
        int incl = g_cnt[i] + g_bpre[blockIdx.x];
        g_off[i + 1] = incl;
        if (i + 1 < NN) g_cursor[i + 1] = incl;
        if (i == 0) { g_off[0] = 0; g_cursor[0] = 0; }
    }
}
__global__ void k_scatter(const int* __restrict__ src, const int* __restrict__ dst) {
    int e = blockIdx.x * blockDim.x + threadIdx.x;
    if (e < NE) {
        int s = src[e], t = dst[e];
        int p = atomicAdd(&g_cursor[t], 1);
        g_csrc[p] = s;
        g_cw[p]   = g_dinv[s] * g_dinv[t];
    }
}

// ============ tensor-core GEMM: hwb[M,128](bf16) = A @ W (3-term bf16 split) ============
// FUSE=0: A = fp32 input x. FUSE=1: A = hpack (hi|lo packed uint32 per feature).
template <int FUSE>
__global__ __launch_bounds__(256, 2) void k_gemm_mma(
    const void* __restrict__ Ain, const uint4* __restrict__ wp,
    uint32_t* __restrict__ outb, int M)
{
    extern __shared__ char smem[];
    uint4* Wp = reinterpret_cast<uint4*>(smem);
    int tid  = threadIdx.x;
    int wid  = tid >> 5;
    int lane = tid & 31;
    int m0   = blockIdx.x * 128;

    #pragma unroll
    for (int i = 0; i < 16; i++) {
        int idx = tid + i * 256;
        int n = idx >> 5, r = idx & 31;
        Wp[n * WPAD + r] = wp[idx];
    }
    __syncthreads();

    int fr = lane >> 2;                    // 0..7
    int q  = lane & 3;                     // 0..3
    int r0 = m0 + wid * 16 + fr;
    int r1 = r0 + 8;
    bool ok0 = r0 < M, ok1 = r1 < M;

    float acc[16][4];
    #pragma unroll
    for (int ni = 0; ni < 16; ni++)
        #pragma unroll
        for (int p = 0; p < 4; p++) acc[ni][p] = 0.f;

    #pragma unroll
    for (int kk = 0; kk < 8; kk++) {
        int kw = kk * 8 + q;               // pair-index within 128-col row
        uint32_t ah[4], al[4];
        if (FUSE) {
            const uint2* H2 = reinterpret_cast<const uint2*>(Ain);
            uint2 u00 = make_uint2(0u, 0u), u01 = u00, u10 = u00, u11 = u00;
            if (ok0) { u00 = H2[(size_t)r0 * 64 + kw]; u01 = H2[(size_t)r0 * 64 + kw + 4]; }
            if (ok1) { u10 = H2[(size_t)r1 * 64 + kw]; u11 = H2[(size_t)r1 * 64 + kw + 4]; }
            ah[0] = __byte_perm(u00.x, u00.y, 0x5410); al[0] = __byte_perm(u00.x, u00.y, 0x7632);
            ah[1] = __byte_perm(u10.x, u10.y, 0x5410); al[1] = __byte_perm(u10.x, u10.y, 0x7632);
            ah[2] = __byte_perm(u01.x, u01.y, 0x5410); al[2] = __byte_perm(u01.x, u01.y, 0x7632);
            ah[3] = __byte_perm(u11.x, u11.y, 0x5410); al[3] = __byte_perm(u11.x, u11.y, 0x7632);
        } else {
            const float2* A2 = reinterpret_cast<const float2*>(Ain);
            float2 v00 = make_float2(0.f, 0.f), v01 = v00, v10 = v00, v11 = v00;
            if (ok0) { v00 = A2[(size_t)r0 * 64 + kw]; v01 = A2[(size_t)r0 * 64 + kw + 4]; }
            if (ok1) { v10 = A2[(size_t)r1 * 64 + kw]; v11 = A2[(size_t)r1 * 64 + kw + 4]; }
            __nv_bfloat162 h; float2 f;
            h = __float22bfloat162_rn(v00); f = __bfloat1622float2(h);
            ah[0] = *reinterpret_cast<uint32_t*>(&h); al[0] = bf2_of(v00.x - f.x, v00.y - f.y);
            h = __float22bfloat162_rn(v10); f = __bfloat1622float2(h);
            ah[1] = *reinterpret_cast<uint32_t*>(&h); al[1] = bf2_of(v10.x - f.x, v10.y - f.y);
            h = __float22bfloat162_rn(v01); f = __bfloat1622float2(h);
            ah[2] = *reinterpret_cast<uint32_t*>(&h); al[2] = bf2_of(v01.x - f.x, v01.y - f.y);
            h = __float22bfloat162_rn(v11); f = __bfloat1622float2(h);
            ah[3] = *reinterpret_cast<uint32_t*>(&h); al[3] = bf2_of(v11.x - f.x, v11.y - f.y);
        }
        #pragma unroll
        for (int ni = 0; ni < 16; ni++) {
            int n = ni * 8 + fr;
            uint4 b = Wp[n * WPAD + kk * 4 + q];
            mma_bf16(acc[ni], ah[0], ah[1], ah[2], ah[3], b.x, b.y);  // hi*W_hi
            mma_bf16(acc[ni], ah[0], ah[1], ah[2], ah[3], b.z, b.w);  // hi*W_lo
            mma_bf16(acc[ni], al[0], al[1], al[2], al[3], b.x, b.y);  // lo*W_hi
        }
    }

    // ---- epilogue: pack fp32 pairs to bf16x2, store ----
    #pragma unroll
    for (int ni = 0; ni < 16; ni++) {
        int cw = ni * 4 + q;               // uint32 index within 64-wide bf16x2 row
        if (ok0) outb[(size_t)r0 * 64 + cw] = bf2_of(acc[ni][0], acc[ni][1]);
        if (ok1) outb[(size_t)r1 * 64 + cw] = bf2_of(acc[ni][2], acc[ni][3]);
    }
}

// ---- CSR aggregation from bf16 rows; fused bias+relu+hi/lo split output ----
__global__ __launch_bounds__(256) void k_agg(const uint2* __restrict__ hwb,
                                             const float* __restrict__ bias,
                                             uint4* __restrict__ hpack)
{
    int gid  = blockIdx.x * blockDim.x + threadIdx.x;
    int n    = gid >> 5;
    int lane = threadIdx.x & 31;
    if (n >= NN) return;
    uint2 sv = hwb[(size_t)n * 32 + lane];
    float2 s0 = bf2f(sv.x), s1 = bf2f(sv.y);
    float w = g_dinv2[n];
    float a0 = s0.x * w, a1 = s0.y * w, a2 = s1.x * w, a3 = s1.y * w;
    int beg = g_off[n], end = g_off[n + 1];
    for (int i = beg; i < end; i++) {
        int   sn = g_csrc[i];
        float we = g_cw[i];
        uint2 v  = __ldg(&hwb[(size_t)sn * 32 + lane]);
        float2 f0 = bf2f(v.x), f1 = bf2f(v.y);
        a0 = fmaf(we, f0.x, a0);
        a1 = fmaf(we, f0.y, a1);
        a2 = fmaf(we, f1.x, a2);
        a3 = fmaf(we, f1.y, a3);
    }
    float4 b4 = reinterpret_cast<const float4*>(bias)[lane];
    uint4 o;
    o.x = packsplit(fmaxf(a0 + b4.x, 0.f));
    o.y = packsplit(fmaxf(a1 + b4.y, 0.f));
    o.z = packsplit(fmaxf(a2 + b4.z, 0.f));
    o.w = packsplit(fmaxf(a3 + b4.w, 0.f));
    hpack[(size_t)n * 32 + lane] = o;
}

// ---------------- pooling (batch is sorted); h already relu+bias'ed in hpack ----------------
__global__ void k_pool(const uint32_t* __restrict__ hp,
                       const int* __restrict__ batch)
{
    int d  = threadIdx.x;
    int n0 = blockIdx.x * 128;
    int n1 = n0 + 128; if (n1 > NN) n1 = NN;
    if (n0 >= NN) return;
    float acc = 0.f;
    int gprev = batch[n0];
    for (int n = n0; n < n1; n++) {
        int g = batch[n];
        if (g != gprev) {
            atomicAdd(&g_pooled[gprev * 128 + d], acc);
            acc = 0.f;
            gprev = g;
        }
        float2 hl = bf2f(hp[(size_t)n * 128 + d]);
        acc += hl.x + hl.y;    // hi + lo reconstruct
    }
    atomicAdd(&g_pooled[gprev * 128 + d], acc);
}

// ---------------- MLP head ----------------
__global__ void k_mlp(const float* __restrict__ in, const float* __restrict__ W,
                      const float* __restrict__ bias, float* __restrict__ out)
{
    __shared__ float row[128];
    int r = blockIdx.x, c = threadIdx.x;
    row[c] = in[r * 128 + c];
    __syncthreads();
    float acc = bias[c];
    #pragma unroll 8
    for (int k = 0; k < 128; k++)
        acc = fmaf(row[k], W[k * 128 + c], acc);
    out[r * 128 + c] = fmaxf(acc, 0.f);
}

__global__ void k_final(const float* __restrict__ z, const float* __restrict__ W3,
                        const float* __restrict__ b3, float* __restrict__ out)
{
    int g = blockIdx.x, t = threadIdx.x;
    float v = z[g * 128 + t] * W3[t];
    #pragma unroll
    for (int o = 16; o > 0; o >>= 1) v += __shfl_down_sync(0xffffffffu, v, o);
    __shared__ float partial[4];
    if ((t & 31) == 0) partial[t >> 5] = v;
    __syncthreads();
    if (t == 0) {
        float s = partial[0] + partial[1] + partial[2] + partial[3] + b3[0];
        out[g] = 1.f / (1.f + expf(-s));
    }
}

// ---------------- launch ----------------
extern "C" void kernel_launch(void* const* d_in, const int* in_sizes, int n_in,
                              void* d_out, int out_size)
{
    const float* x     = (const float*)d_in[0];
    const int*   ei    = (const int*)d_in[1];     // int32 (JAX x64 disabled)
    const int*   src   = ei;
    const int*   dst   = ei + NE;
    const int*   batch = (const int*)d_in[2];
    const float* convW = (const float*)d_in[3];
    const float* convB = (const float*)d_in[4];
    const float* W1    = (const float*)d_in[5];
    const float* b1    = (const float*)d_in[6];
    const float* W2    = (const float*)d_in[7];
    const float* b2    = (const float*)d_in[8];
    const float* W3    = (const float*)d_in[9];
    const float* b3    = (const float*)d_in[10];
    float* out = (float*)d_out;

    uint2* hwb;  uint4* hpk;  uint4* wpk;
    float *pooled, *z1, *z2;
    cudaGetSymbolAddress((void**)&hwb,    g_hwb);
    cudaGetSymbolAddress((void**)&hpk,    g_hpack);
    cudaGetSymbolAddress((void**)&wpk,    g_wpack);
    cudaGetSymbolAddress((void**)&pooled, g_pooled);
    cudaGetSymbolAddress((void**)&z1,     g_z1);
    cudaGetSymbolAddress((void**)&z2,     g_z2);

    static bool attr_done = false;
    if (!attr_done) {
        cudaFuncSetAttribute(k_gemm_mma<0>, cudaFuncAttributeMaxDynamicSharedMemorySize, SMEM_MMA);
        cudaFuncSetAttribute(k_gemm_mma<1>, cudaFuncAttributeMaxDynamicSharedMemorySize, SMEM_MMA);
        attr_done = true;
    }

    // ---- setup: init (+Wpack), degree, scan, scatter ----
    k_init   <<<(NN + 255) / 256, 256>>>(convW);
    k_cnt    <<<(NE + 255) / 256, 256>>>(dst);
    k_scan1  <<<NSB, SCAN_B>>>();
    k_scan2  <<<1, 128>>>();
    k_scan3  <<<NSB, SCAN_B>>>();
    k_scatter<<<(NE + 255) / 256, 256>>>(src, dst);

    // ---- 4 GCN layers ----
    uint32_t* hwb32 = reinterpret_cast<uint32_t*>(hwb);
    k_gemm_mma<0><<<NTILES, 256, SMEM_MMA>>>(x, wpk, hwb32, NN);
    k_agg<<<(NN * 32 + 255) / 256, 256>>>(hwb, convB, hpk);
    for (int l = 1; l < 4; l++) {
        k_gemm_mma<1><<<NTILES, 256, SMEM_MMA>>>(hpk, wpk + (size_t)l * 4096, hwb32, NN);
        k_agg<<<(NN * 32 + 255) / 256, 256>>>(hwb, convB + (size_t)l * DD, hpk);
    }

    // ---- pooling + MLP head ----
    k_pool<<<(NN + 127) / 128, 128>>>(reinterpret_cast<const uint32_t*>(hpk), batch);
    k_mlp<<<NG, 128>>>(pooled, W1, b1, z1);
    k_mlp<<<NG, 128>>>(z1, W2, b2, z2);
    k_final<<<NG, 128>>>(z2, W3, b3, out);
}

// round 9
// speedup vs baseline: 3.8448x; 1.1312x over previous
#include <cuda_runtime.h>
#include <cuda_bf16.h>
#include <math.h>
#include <cstdint>

#define NN   100000
#define NE   640000
#define DD   128
#define NG   512
#define SCAN_B 1024
#define NSB  ((NN + SCAN_B - 1) / SCAN_B)   // 98 scan blocks
#define NTILES ((NN + 127) / 128)           // 782

// ---------------- scratch (no allocations allowed) ----------------
__device__ uint2 g_hwb[(size_t)NN * 32];    // h@W in bf16x2 (25.6MB)
__device__ uint2 g_hbf[(size_t)NN * 32];    // relu(agg+b) in bf16x2 (25.6MB)
__device__ float g_dinv[NN];
__device__ float g_dinv2[NN];
__device__ int   g_cnt [NN];
__device__ int   g_off [NN + 1];
__device__ int   g_cursor[NN];
__device__ int   g_csrc[NE];
__device__ float g_cw  [NE];
__device__ int   g_bsum[NSB];
__device__ int   g_bpre[NSB];
__device__ float g_pooled[NG * DD];
__device__ float g_z1[NG * DD];
__device__ float g_z2[NG * DD];
// packed W fragments: [layer][n(128)][kk(8)][q(4)] uint4 = {hi@kb, hi@kb+4, lo@kb, lo@kb+4}
__device__ uint4 g_wpack[4 * 128 * 8 * 4];

// ---------------- smem layout for MMA GEMM ----------------
#define WPAD 36                          // uint4 per n-row in smem (padded from 32)
#define SMEM_MMA (128 * WPAD * 16)       // 73728

__device__ __forceinline__ void mma_bf16(float c[4], uint32_t a0, uint32_t a1,
                                         uint32_t a2, uint32_t a3,
                                         uint32_t b0, uint32_t b1) {
    asm volatile(
        "mma.sync.aligned.m16n8k16.row.col.f32.bf16.bf16.f32 "
        "{%0,%1,%2,%3}, {%4,%5,%6,%7}, {%8,%9}, {%0,%1,%2,%3};"
        : "+f"(c[0]), "+f"(c[1]), "+f"(c[2]), "+f"(c[3])
        : "r"(a0), "r"(a1), "r"(a2), "r"(a3), "r"(b0), "r"(b1));
}

__device__ __forceinline__ uint32_t bf2_of(float a, float b) {
    __nv_bfloat162 t = __float22bfloat162_rn(make_float2(a, b));
    return *reinterpret_cast<uint32_t*>(&t);
}
__device__ __forceinline__ float2 bf2f(uint32_t u) {
    __nv_bfloat162 h = *reinterpret_cast<__nv_bfloat162*>(&u);
    return __bfloat1622float2(h);
}

// ---------------- init: zero cnt + zero pooled + W pack (one kernel) ----------------
__global__ void k_init(const float* __restrict__ convW) {
    int idx = blockIdx.x * 256 + threadIdx.x;
    if (idx < NN) g_cnt[idx] = 0;
    if (idx < NG * DD) g_pooled[idx] = 0.f;
    if (idx < 16384) {   // 4*128*8*4 W fragments
        int q  = idx & 3;
        int kk = (idx >> 2) & 7;
        int n  = (idx >> 5) & 127;
        int l  = idx >> 12;
        int k0 = kk * 16 + q * 2;
        const float* Wl = convW + (size_t)l * 16384;
        float w00 = Wl[(size_t)(k0    ) * 128 + n], w01 = Wl[(size_t)(k0 + 1) * 128 + n];
        float w10 = Wl[(size_t)(k0 + 8) * 128 + n], w11 = Wl[(size_t)(k0 + 9) * 128 + n];
        __nv_bfloat162 h0 = __float22bfloat162_rn(make_float2(w00, w01));
        __nv_bfloat162 h1 = __float22bfloat162_rn(make_float2(w10, w11));
        float2 f0 = __bfloat1622float2(h0), f1 = __bfloat1622float2(h1);
        uint4 v;
        v.x = *reinterpret_cast<uint32_t*>(&h0);
        v.y = *reinterpret_cast<uint32_t*>(&h1);
        v.z = bf2_of(w00 - f0.x, w01 - f0.y);
        v.w = bf2_of(w10 - f1.x, w11 - f1.y);
        g_wpack[idx] = v;
    }
}

__global__ void k_cnt(const int* __restrict__ dst) {
    int e = blockIdx.x * blockDim.x + threadIdx.x;
    if (e < NE) atomicAdd(&g_cnt[dst[e]], 1);
}

// ---------------- scan (CSR offsets); dinv fused ----------------
__global__ __launch_bounds__(SCAN_B) void k_scan1() {
    __shared__ int s[SCAN_B];
    int t = threadIdx.x;
    int i = blockIdx.x * SCAN_B + t;
    int v = (i < NN) ? g_cnt[i] : 0;
    if (i < NN) {
        float deg = (float)(v + 1);
        g_dinv[i]  = rsqrtf(deg);
        g_dinv2[i] = 1.0f / deg;
    }
    s[t] = v;
    __syncthreads();
    #pragma unroll
    for (int o = 1; o < SCAN_B; o <<= 1) {
        int x = (t >= o) ? s[t - o] : 0;
        __syncthreads();
        s[t] += x;
        __syncthreads();
    }
    if (i < NN) g_cnt[i] = s[t];
    if (t == SCAN_B - 1) g_bsum[blockIdx.x] = s[t];
}
__global__ void k_scan2() {
    __shared__ int s[128];
    int t = threadIdx.x;
    int v = (t < NSB) ? g_bsum[t] : 0;
    s[t] = v;
    __syncthreads();
    #pragma unroll
    for (int o = 1; o < 128; o <<= 1) {
        int x = (t >= o) ? s[t - o] : 0;
        __syncthreads();
        s[t] += x;
        __syncthreads();
    }
    if (t < NSB) g_bpre[t] = s[t] - v;   // exclusive
}
__global__ __launch_bounds__(SCAN_B) void k_scan3() {
    int i = blockIdx.x * SCAN_B + threadIdx.x;
    if (i < NN) {
        int incl = g_cnt[i] + g_bpre[blockIdx.x];
        g_off[i + 1] = incl;
        if (i + 1 < NN) g_cursor[i + 1] = incl;
        if (i == 0) { g_off[0] = 0; g_cursor[0] = 0; }
    }
}
__global__ void k_scatter(const int* __restrict__ src, const int* __restrict__ dst) {
    int e = blockIdx.x * blockDim.x + threadIdx.x;
    if (e < NE) {
        int s = src[e], t = dst[e];
        int p = atomicAdd(&g_cursor[t], 1);
        g_csrc[p] = s;
        g_cw[p]   = g_dinv[s] * g_dinv[t];
    }
}

// ============ tensor-core GEMM: hwb[M,128](bf16) = A @ W ============
// FUSE=0: A = fp32 input x (3-term split: Ahi*Whi + Ahi*Wlo + Alo*Whi).
// FUSE=1: A = hbf (exact bf16): 2-term split (A*Whi + A*Wlo).
template <int FUSE>
__global__ __launch_bounds__(256, 2) void k_gemm_mma(
    const void* __restrict__ Ain, const uint4* __restrict__ wp,
    uint32_t* __restrict__ outb, int M)
{
    extern __shared__ char smem[];
    uint4* Wp = reinterpret_cast<uint4*>(smem);
    int tid  = threadIdx.x;
    int wid  = tid >> 5;
    int lane = tid & 31;
    int m0   = blockIdx.x * 128;

    #pragma unroll
    for (int i = 0; i < 16; i++) {
        int idx = tid + i * 256;
        int n = idx >> 5, r = idx & 31;
        Wp[n * WPAD + r] = wp[idx];
    }
    __syncthreads();

    int fr = lane >> 2;                    // 0..7
    int q  = lane & 3;                     // 0..3
    int r0 = m0 + wid * 16 + fr;
    int r1 = r0 + 8;
    bool ok0 = r0 < M, ok1 = r1 < M;

    float acc[16][4];
    #pragma unroll
    for (int ni = 0; ni < 16; ni++)
        #pragma unroll
        for (int p = 0; p < 4; p++) acc[ni][p] = 0.f;

    #pragma unroll
    for (int kk = 0; kk < 8; kk++) {
        int kw = kk * 8 + q;               // bf16x2-word / float2-pair index in row
        uint32_t ah[4], al[4];
        if (FUSE) {
            const uint32_t* H = reinterpret_cast<const uint32_t*>(Ain);
            ah[0] = ok0 ? H[(size_t)r0 * 64 + kw]     : 0u;
            ah[2] = ok0 ? H[(size_t)r0 * 64 + kw + 4] : 0u;
            ah[1] = ok1 ? H[(size_t)r1 * 64 + kw]     : 0u;
            ah[3] = ok1 ? H[(size_t)r1 * 64 + kw + 4] : 0u;
        } else {
            const float2* A2 = reinterpret_cast<const float2*>(Ain);
            float2 v00 = make_float2(0.f, 0.f), v01 = v00, v10 = v00, v11 = v00;
            if (ok0) { v00 = A2[(size_t)r0 * 64 + kw]; v01 = A2[(size_t)r0 * 64 + kw + 4]; }
            if (ok1) { v10 = A2[(size_t)r1 * 64 + kw]; v11 = A2[(size_t)r1 * 64 + kw + 4]; }
            __nv_bfloat162 h; float2 f;
            h = __float22bfloat162_rn(v00); f = __bfloat1622float2(h);
            ah[0] = *reinterpret_cast<uint32_t*>(&h); al[0] = bf2_of(v00.x - f.x, v00.y - f.y);
            h = __float22bfloat162_rn(v10); f = __bfloat1622float2(h);
            ah[1] = *reinterpret_cast<uint32_t*>(&h); al[1] = bf2_of(v10.x - f.x, v10.y - f.y);
            h = __float22bfloat162_rn(v01); f = __bfloat1622float2(h);
            ah[2] = *reinterpret_cast<uint32_t*>(&h); al[2] = bf2_of(v01.x - f.x, v01.y - f.y);
            h = __float22bfloat162_rn(v11); f = __bfloat1622float2(h);
            ah[3] = *reinterpret_cast<uint32_t*>(&h); al[3] = bf2_of(v11.x - f.x, v11.y - f.y);
        }
        #pragma unroll
        for (int ni = 0; ni < 16; ni++) {
            int n = ni * 8 + fr;
            uint4 b = Wp[n * WPAD + kk * 4 + q];
            mma_bf16(acc[ni], ah[0], ah[1], ah[2], ah[3], b.x, b.y);      // A_hi * W_hi
            mma_bf16(acc[ni], ah[0], ah[1], ah[2], ah[3], b.z, b.w);      // A_hi * W_lo
            if (!FUSE)
                mma_bf16(acc[ni], al[0], al[1], al[2], al[3], b.x, b.y);  // A_lo * W_hi
        }
    }

    // ---- epilogue: pack fp32 pairs to bf16x2, store ----
    #pragma unroll
    for (int ni = 0; ni < 16; ni++) {
        int cw = ni * 4 + q;               // uint32 index within 64-wide bf16x2 row
        if (ok0) outb[(size_t)r0 * 64 + cw] = bf2_of(acc[ni][0], acc[ni][1]);
        if (ok1) outb[(size_t)r1 * 64 + cw] = bf2_of(acc[ni][2], acc[ni][3]);
    }
}

// ---- CSR aggregation from bf16 rows; fused bias+relu, bf16 output ----
__global__ __launch_bounds__(256) void k_agg(const uint2* __restrict__ hwb,
                                             const float* __restrict__ bias,
                                             uint2* __restrict__ hbf)
{
    int gid  = blockIdx.x * blockDim.x + threadIdx.x;
    int n    = gid >> 5;
    int lane = threadIdx.x & 31;
    if (n >= NN) return;
    uint2 sv = hwb[(size_t)n * 32 + lane];
    float2 s0 = bf2f(sv.x), s1 = bf2f(sv.y);
    float w = g_dinv2[n];
    float a0 = s0.x * w, a1 = s0.y * w, a2 = s1.x * w, a3 = s1.y * w;
    int beg = g_off[n], end = g_off[n + 1];
    for (int i = beg; i < end; i++) {
        int   sn = g_csrc[i];
        float we = g_cw[i];
        uint2 v  = __ldg(&hwb[(size_t)sn * 32 + lane]);
        float2 f0 = bf2f(v.x), f1 = bf2f(v.y);
        a0 = fmaf(we, f0.x, a0);
        a1 = fmaf(we, f0.y, a1);
        a2 = fmaf(we, f1.x, a2);
        a3 = fmaf(we, f1.y, a3);
    }
    float4 b4 = reinterpret_cast<const float4*>(bias)[lane];
    uint2 o;
    o.x = bf2_of(fmaxf(a0 + b4.x, 0.f), fmaxf(a1 + b4.y, 0.f));
    o.y = bf2_of(fmaxf(a2 + b4.z, 0.f), fmaxf(a3 + b4.w, 0.f));
    hbf[(size_t)n * 32 + lane] = o;
}

// ---------------- pooling (batch is sorted); h = packed bf16 ----------------
__global__ void k_pool(const uint32_t* __restrict__ hp,
                       const int* __restrict__ batch)
{
    int d  = threadIdx.x;                 // feature 0..127
    int n0 = blockIdx.x * 128;
    int n1 = n0 + 128; if (n1 > NN) n1 = NN;
    if (n0 >= NN) return;
    int  wsel = d >> 1;                   // word index
    bool hi   = d & 1;
    float acc = 0.f;
    int gprev = batch[n0];
    for (int n = n0; n < n1; n++) {
        int g = batch[n];
        if (g != gprev) {
            atomicAdd(&g_pooled[gprev * 128 + d], acc);
            acc = 0.f;
            gprev = g;
        }
        float2 hl = bf2f(hp[(size_t)n * 64 + wsel]);
        acc += hi ? hl.y : hl.x;
    }
    atomicAdd(&g_pooled[gprev * 128 + d], acc);
}

// ---------------- MLP head ----------------
__global__ void k_mlp(const float* __restrict__ in, const float* __restrict__ W,
                      const float* __restrict__ bias, float* __restrict__ out)
{
    __shared__ float row[128];
    int r = blockIdx.x, c = threadIdx.x;
    row[c] = in[r * 128 + c];
    __syncthreads();
    float acc = bias[c];
    #pragma unroll 8
    for (int k = 0; k < 128; k++)
        acc = fmaf(row[k], W[k * 128 + c], acc);
    out[r * 128 + c] = fmaxf(acc, 0.f);
}

__global__ void k_final(const float* __restrict__ z, const float* __restrict__ W3,
                        const float* __restrict__ b3, float* __restrict__ out)
{
    int g = blockIdx.x, t = threadIdx.x;
    float v = z[g * 128 + t] * W3[t];
    #pragma unroll
    for (int o = 16; o > 0; o >>= 1) v += __shfl_down_sync(0xffffffffu, v, o);
    __shared__ float partial[4];
    if ((t & 31) == 0) partial[t >> 5] = v;
    __syncthreads();
    if (t == 0) {
        float s = partial[0] + partial[1] + partial[2] + partial[3] + b3[0];
        out[g] = 1.f / (1.f + expf(-s));
    }
}

// ---------------- launch ----------------
extern "C" void kernel_launch(void* const* d_in, const int* in_sizes, int n_in,
                              void* d_out, int out_size)
{
    const float* x     = (const float*)d_in[0];
    const int*   ei    = (const int*)d_in[1];     // int32 (JAX x64 disabled)
    const int*   src   = ei;
    const int*   dst   = ei + NE;
    const int*   batch = (const int*)d_in[2];
    const float* convW = (const float*)d_in[3];
    const float* convB = (const float*)d_in[4];
    const float* W1    = (const float*)d_in[5];
    const float* b1    = (const float*)d_in[6];
    const float* W2    = (const float*)d_in[7];
    const float* b2    = (const float*)d_in[8];
    const float* W3    = (const float*)d_in[9];
    const float* b3    = (const float*)d_in[10];
    float* out = (float*)d_out;

    uint2 *hwb, *hbf;  uint4* wpk;
    float *pooled, *z1, *z2;
    cudaGetSymbolAddress((void**)&hwb,    g_hwb);
    cudaGetSymbolAddress((void**)&hbf,    g_hbf);
    cudaGetSymbolAddress((void**)&wpk,    g_wpack);
    cudaGetSymbolAddress((void**)&pooled, g_pooled);
    cudaGetSymbolAddress((void**)&z1,     g_z1);
    cudaGetSymbolAddress((void**)&z2,     g_z2);

    static bool attr_done = false;
    if (!attr_done) {
        cudaFuncSetAttribute(k_gemm_mma<0>, cudaFuncAttributeMaxDynamicSharedMemorySize, SMEM_MMA);
        cudaFuncSetAttribute(k_gemm_mma<1>, cudaFuncAttributeMaxDynamicSharedMemorySize, SMEM_MMA);
        attr_done = true;
    }

    // ---- setup: init (+Wpack), degree, scan, scatter ----
    k_init   <<<(NN + 255) / 256, 256>>>(convW);
    k_cnt    <<<(NE + 255) / 256, 256>>>(dst);
    k_scan1  <<<NSB, SCAN_B>>>();
    k_scan2  <<<1, 128>>>();
    k_scan3  <<<NSB, SCAN_B>>>();
    k_scatter<<<(NE + 255) / 256, 256>>>(src, dst);

    // ---- 4 GCN layers ----
    uint32_t* hwb32 = reinterpret_cast<uint32_t*>(hwb);
    k_gemm_mma<0><<<NTILES, 256, SMEM_MMA>>>(x, wpk, hwb32, NN);
    k_agg<<<(NN * 32 + 255) / 256, 256>>>(hwb, convB, hbf);
    for (int l = 1; l < 4; l++) {
        k_gemm_mma<1><<<NTILES, 256, SMEM_MMA>>>(hbf, wpk + (size_t)l * 4096, hwb32, NN);
        k_agg<<<(NN * 32 + 255) / 256, 256>>>(hwb, convB + (size_t)l * DD, hbf);
    }

    // ---- pooling + MLP head ----
    k_pool<<<(NN + 127) / 128, 128>>>(reinterpret_cast<const uint32_t*>(hbf), batch);
    k_mlp<<<NG, 128>>>(pooled, W1, b1, z1);
    k_mlp<<<NG, 128>>>(z1, W2, b2, z2);
    k_final<<<NG, 128>>>(z2, W3, b3, out);
}

// round 10
// speedup vs baseline: 3.9056x; 1.0158x over previous
#include <cuda_runtime.h>
#include <cuda_bf16.h>
#include <math.h>
#include <cstdint>

#define NN   100000
#define NE   640000
#define DD   128
#define NG   512
#define SCAN_B 1024
#define NSB  ((NN + SCAN_B - 1) / SCAN_B)   // 98 scan blocks
#define NTILES ((NN + 127) / 128)           // 782

// ---------------- scratch (no allocations allowed) ----------------
__device__ uint2 g_hwb[(size_t)NN * 32];    // h@W in bf16x2 (25.6MB)
__device__ uint2 g_hbf[(size_t)NN * 32];    // relu(agg+b) in bf16x2 (25.6MB)
__device__ float g_dinv[NN];
__device__ float g_dinv2[NN];
__device__ int   g_cnt [NN];
__device__ int   g_off [NN + 1];
__device__ int   g_cursor[NN];
__device__ int   g_csrc[NE];
__device__ float g_cw  [NE];
__device__ int   g_bsum[NSB];
__device__ float g_pooled[NG * DD];
// packed W fragments: [layer][n(128)][kk(8)][q(4)] uint4 = {hi@kb, hi@kb+4, lo@kb, lo@kb+4}
__device__ uint4 g_wpack[4 * 128 * 8 * 4];

// ---------------- smem layout for MMA GEMM ----------------
#define WPAD 36                          // uint4 per n-row in smem (padded from 32)
#define SMEM_MMA (128 * WPAD * 16)       // 73728

__device__ __forceinline__ void mma_bf16(float c[4], uint32_t a0, uint32_t a1,
                                         uint32_t a2, uint32_t a3,
                                         uint32_t b0, uint32_t b1) {
    asm volatile(
        "mma.sync.aligned.m16n8k16.row.col.f32.bf16.bf16.f32 "
        "{%0,%1,%2,%3}, {%4,%5,%6,%7}, {%8,%9}, {%0,%1,%2,%3};"
        : "+f"(c[0]), "+f"(c[1]), "+f"(c[2]), "+f"(c[3])
        : "r"(a0), "r"(a1), "r"(a2), "r"(a3), "r"(b0), "r"(b1));
}

__device__ __forceinline__ uint32_t bf2_of(float a, float b) {
    __nv_bfloat162 t = __float22bfloat162_rn(make_float2(a, b));
    return *reinterpret_cast<uint32_t*>(&t);
}
__device__ __forceinline__ float2 bf2f(uint32_t u) {
    __nv_bfloat162 h = *reinterpret_cast<__nv_bfloat162*>(&u);
    return __bfloat1622float2(h);
}

// ---------------- init: zero cnt + zero pooled + W pack (one kernel) ----------------
__global__ void k_init(const float* __restrict__ convW) {
    int idx = blockIdx.x * 256 + threadIdx.x;
    if (idx < NN) g_cnt[idx] = 0;
    if (idx < NG * DD) g_pooled[idx] = 0.f;
    if (idx < 16384) {   // 4*128*8*4 W fragments
        int q  = idx & 3;
        int kk = (idx >> 2) & 7;
        int n  = (idx >> 5) & 127;
        int l  = idx >> 12;
        int k0 = kk * 16 + q * 2;
        const float* Wl = convW + (size_t)l * 16384;
        float w00 = Wl[(size_t)(k0    ) * 128 + n], w01 = Wl[(size_t)(k0 + 1) * 128 + n];
        float w10 = Wl[(size_t)(k0 + 8) * 128 + n], w11 = Wl[(size_t)(k0 + 9) * 128 + n];
        __nv_bfloat162 h0 = __float22bfloat162_rn(make_float2(w00, w01));
        __nv_bfloat162 h1 = __float22bfloat162_rn(make_float2(w10, w11));
        float2 f0 = __bfloat1622float2(h0), f1 = __bfloat1622float2(h1);
        uint4 v;
        v.x = *reinterpret_cast<uint32_t*>(&h0);
        v.y = *reinterpret_cast<uint32_t*>(&h1);
        v.z = bf2_of(w00 - f0.x, w01 - f0.y);
        v.w = bf2_of(w10 - f1.x, w11 - f1.y);
        g_wpack[idx] = v;
    }
}

__global__ void k_cnt(const int* __restrict__ dst) {
    int e = blockIdx.x * blockDim.x + threadIdx.x;
    if (e < NE) atomicAdd(&g_cnt[dst[e]], 1);
}

// ---------------- scan (CSR offsets); dinv fused ----------------
__global__ __launch_bounds__(SCAN_B) void k_scan1() {
    __shared__ int s[SCAN_B];
    int t = threadIdx.x;
    int i = blockIdx.x * SCAN_B + t;
    int v = (i < NN) ? g_cnt[i] : 0;
    if (i < NN) {
        float deg = (float)(v + 1);
        g_dinv[i]  = rsqrtf(deg);
        g_dinv2[i] = 1.0f / deg;
    }
    s[t] = v;
    __syncthreads();
    #pragma unroll
    for (int o = 1; o < SCAN_B; o <<= 1) {
        int x = (t >= o) ? s[t - o] : 0;
        __syncthreads();
        s[t] += x;
        __syncthreads();
    }
    if (i < NN) g_cnt[i] = s[t];
    if (t == SCAN_B - 1) g_bsum[blockIdx.x] = s[t];
}
// scan3 also computes this block's exclusive prefix of bsum (scan2 folded in)
__global__ __launch_bounds__(SCAN_B) void k_scan3() {
    __shared__ int partial[32];
    __shared__ int pre_s;
    int t = threadIdx.x;
    int v = (t < NSB && t < blockIdx.x) ? g_bsum[t] : 0;
    #pragma unroll
    for (int o = 16; o > 0; o >>= 1) v += __shfl_down_sync(0xffffffffu, v, o);
    if ((t & 31) == 0) partial[t >> 5] = v;
    __syncthreads();
    if (t == 0) {
        int s = 0;
        #pragma unroll
        for (int w = 0; w < SCAN_B / 32; w++) s += partial[w];
        pre_s = s;
    }
    __syncthreads();
    int pre = pre_s;
    int i = blockIdx.x * SCAN_B + t;
    if (i < NN) {
        int incl = g_cnt[i] + pre;
        g_off[i + 1] = incl;
        if (i + 1 < NN) g_cursor[i + 1] = incl;
        if (i == 0) { g_off[0] = 0; g_cursor[0] = 0; }
    }
}
__global__ void k_scatter(const int* __restrict__ src, const int* __restrict__ dst) {
    int e = blockIdx.x * blockDim.x + threadIdx.x;
    if (e < NE) {
        int s = src[e], t = dst[e];
        int p = atomicAdd(&g_cursor[t], 1);
        g_csrc[p] = s;
        g_cw[p]   = g_dinv[s] * g_dinv[t];
    }
}

// ============ tensor-core GEMM: hwb[M,128](bf16) = A @ W ============
// FUSE=0: A = fp32 input x (3-term split). FUSE=1: A = hbf (bf16, 2-term split).
template <int FUSE>
__global__ __launch_bounds__(256, 2) void k_gemm_mma(
    const void* __restrict__ Ain, const uint4* __restrict__ wp,
    uint32_t* __restrict__ outb, int M)
{
    extern __shared__ char smem[];
    uint4* Wp = reinterpret_cast<uint4*>(smem);
    int tid  = threadIdx.x;
    int wid  = tid >> 5;
    int lane = tid & 31;
    int m0   = blockIdx.x * 128;

    #pragma unroll
    for (int i = 0; i < 16; i++) {
        int idx = tid + i * 256;
        int n = idx >> 5, r = idx & 31;
        Wp[n * WPAD + r] = wp[idx];
    }
    __syncthreads();

    int fr = lane >> 2;                    // 0..7
    int q  = lane & 3;                     // 0..3
    int r0 = m0 + wid * 16 + fr;
    int r1 = r0 + 8;
    bool ok0 = r0 < M, ok1 = r1 < M;

    float acc[16][4];
    #pragma unroll
    for (int ni = 0; ni < 16; ni++)
        #pragma unroll
        for (int p = 0; p < 4; p++) acc[ni][p] = 0.f;

    #pragma unroll
    for (int kk = 0; kk < 8; kk++) {
        int kw = kk * 8 + q;
        uint32_t ah[4], al[4];
        if (FUSE) {
            const uint32_t* H = reinterpret_cast<const uint32_t*>(Ain);
            ah[0] = ok0 ? H[(size_t)r0 * 64 + kw]     : 0u;
            ah[2] = ok0 ? H[(size_t)r0 * 64 + kw + 4] : 0u;
            ah[1] = ok1 ? H[(size_t)r1 * 64 + kw]     : 0u;
            ah[3] = ok1 ? H[(size_t)r1 * 64 + kw + 4] : 0u;
        } else {
            const float2* A2 = reinterpret_cast<const float2*>(Ain);
            float2 v00 = make_float2(0.f, 0.f), v01 = v00, v10 = v00, v11 = v00;
            if (ok0) { v00 = A2[(size_t)r0 * 64 + kw]; v01 = A2[(size_t)r0 * 64 + kw + 4]; }
            if (ok1) { v10 = A2[(size_t)r1 * 64 + kw]; v11 = A2[(size_t)r1 * 64 + kw + 4]; }
            __nv_bfloat162 h; float2 f;
            h = __float22bfloat162_rn(v00); f = __bfloat1622float2(h);
            ah[0] = *reinterpret_cast<uint32_t*>(&h); al[0] = bf2_of(v00.x - f.x, v00.y - f.y);
            h = __float22bfloat162_rn(v10); f = __bfloat1622float2(h);
            ah[1] = *reinterpret_cast<uint32_t*>(&h); al[1] = bf2_of(v10.x - f.x, v10.y - f.y);
            h = __float22bfloat162_rn(v01); f = __bfloat1622float2(h);
            ah[2] = *reinterpret_cast<uint32_t*>(&h); al[2] = bf2_of(v01.x - f.x, v01.y - f.y);
            h = __float22bfloat162_rn(v11); f = __bfloat1622float2(h);
            ah[3] = *reinterpret_cast<uint32_t*>(&h); al[3] = bf2_of(v11.x - f.x, v11.y - f.y);
        }
        #pragma unroll
        for (int ni = 0; ni < 16; ni++) {
            int n = ni * 8 + fr;
            uint4 b = Wp[n * WPAD + kk * 4 + q];
            mma_bf16(acc[ni], ah[0], ah[1], ah[2], ah[3], b.x, b.y);      // A_hi * W_hi
            mma_bf16(acc[ni], ah[0], ah[1], ah[2], ah[3], b.z, b.w);      // A_hi * W_lo
            if (!FUSE)
                mma_bf16(acc[ni], al[0], al[1], al[2], al[3], b.x, b.y);  // A_lo * W_hi
        }
    }

    #pragma unroll
    for (int ni = 0; ni < 16; ni++) {
        int cw = ni * 4 + q;
        if (ok0) outb[(size_t)r0 * 64 + cw] = bf2_of(acc[ni][0], acc[ni][1]);
        if (ok1) outb[(size_t)r1 * 64 + cw] = bf2_of(acc[ni][2], acc[ni][3]);
    }
}

// ---- CSR aggregation, 4-way unrolled (MLP=4); fused bias+relu, bf16 out ----
__global__ __launch_bounds__(256) void k_agg(const uint2* __restrict__ hwb,
                                             const float* __restrict__ bias,
                                             uint2* __restrict__ hbf)
{
    int gid  = blockIdx.x * blockDim.x + threadIdx.x;
    int n    = gid >> 5;
    int lane = threadIdx.x & 31;
    if (n >= NN) return;
    uint2 sv = hwb[(size_t)n * 32 + lane];
    float2 s0 = bf2f(sv.x), s1 = bf2f(sv.y);
    float w = g_dinv2[n];
    float a0 = s0.x * w, a1 = s0.y * w, a2 = s1.x * w, a3 = s1.y * w;
    int i = g_off[n], end = g_off[n + 1];

    for (; i + 4 <= end; i += 4) {
        int   s0i = g_csrc[i],     s1i = g_csrc[i + 1];
        int   s2i = g_csrc[i + 2], s3i = g_csrc[i + 3];
        float w0 = g_cw[i],     w1 = g_cw[i + 1];
        float w2 = g_cw[i + 2], w3 = g_cw[i + 3];
        uint2 v0 = __ldg(&hwb[(size_t)s0i * 32 + lane]);
        uint2 v1 = __ldg(&hwb[(size_t)s1i * 32 + lane]);
        uint2 v2 = __ldg(&hwb[(size_t)s2i * 32 + lane]);
        uint2 v3 = __ldg(&hwb[(size_t)s3i * 32 + lane]);
        float2 f;
        f = bf2f(v0.x); a0 = fmaf(w0, f.x, a0); a1 = fmaf(w0, f.y, a1);
        f = bf2f(v0.y); a2 = fmaf(w0, f.x, a2); a3 = fmaf(w0, f.y, a3);
        f = bf2f(v1.x); a0 = fmaf(w1, f.x, a0); a1 = fmaf(w1, f.y, a1);
        f = bf2f(v1.y); a2 = fmaf(w1, f.x, a2); a3 = fmaf(w1, f.y, a3);
        f = bf2f(v2.x); a0 = fmaf(w2, f.x, a0); a1 = fmaf(w2, f.y, a1);
        f = bf2f(v2.y); a2 = fmaf(w2, f.x, a2); a3 = fmaf(w2, f.y, a3);
        f = bf2f(v3.x); a0 = fmaf(w3, f.x, a0); a1 = fmaf(w3, f.y, a1);
        f = bf2f(v3.y); a2 = fmaf(w3, f.x, a2); a3 = fmaf(w3, f.y, a3);
    }
    for (; i < end; i++) {
        int   sn = g_csrc[i];
        float we = g_cw[i];
        uint2 v  = __ldg(&hwb[(size_t)sn * 32 + lane]);
        float2 f0 = bf2f(v.x), f1 = bf2f(v.y);
        a0 = fmaf(we, f0.x, a0);
        a1 = fmaf(we, f0.y, a1);
        a2 = fmaf(we, f1.x, a2);
        a3 = fmaf(we, f1.y, a3);
    }
    float4 b4 = reinterpret_cast<const float4*>(bias)[lane];
    uint2 o;
    o.x = bf2_of(fmaxf(a0 + b4.x, 0.f), fmaxf(a1 + b4.y, 0.f));
    o.y = bf2_of(fmaxf(a2 + b4.z, 0.f), fmaxf(a3 + b4.w, 0.f));
    hbf[(size_t)n * 32 + lane] = o;
}

// ---------------- pooling (batch is sorted); h = packed bf16 ----------------
__global__ void k_pool(const uint32_t* __restrict__ hp,
                       const int* __restrict__ batch)
{
    int d  = threadIdx.x;
    int n0 = blockIdx.x * 128;
    int n1 = n0 + 128; if (n1 > NN) n1 = NN;
    if (n0 >= NN) return;
    int  wsel = d >> 1;
    bool hi   = d & 1;
    float acc = 0.f;
    int gprev = batch[n0];
    for (int n = n0; n < n1; n++) {
        int g = batch[n];
        if (g != gprev) {
            atomicAdd(&g_pooled[gprev * 128 + d], acc);
            acc = 0.f;
            gprev = g;
        }
        float2 hl = bf2f(hp[(size_t)n * 64 + wsel]);
        acc += hi ? hl.y : hl.x;
    }
    atomicAdd(&g_pooled[gprev * 128 + d], acc);
}

// ---------------- fused MLP head: z1 -> z2 -> sigmoid, one block per graph ----------------
__global__ void k_head(const float* __restrict__ W1, const float* __restrict__ b1,
                       const float* __restrict__ W2, const float* __restrict__ b2,
                       const float* __restrict__ W3, const float* __restrict__ b3,
                       float* __restrict__ out)
{
    __shared__ float buf[128];
    __shared__ float partial[4];
    int g = blockIdx.x, c = threadIdx.x;
    buf[c] = g_pooled[g * 128 + c];
    __syncthreads();
    float acc = b1[c];
    #pragma unroll 8
    for (int k = 0; k < 128; k++)
        acc = fmaf(buf[k], W1[k * 128 + c], acc);
    float z1 = fmaxf(acc, 0.f);
    __syncthreads();
    buf[c] = z1;
    __syncthreads();
    acc = b2[c];
    #pragma unroll 8
    for (int k = 0; k < 128; k++)
        acc = fmaf(buf[k], W2[k * 128 + c], acc);
    float z2 = fmaxf(acc, 0.f);
    float v = z2 * W3[c];
    #pragma unroll
    for (int o = 16; o > 0; o >>= 1) v += __shfl_down_sync(0xffffffffu, v, o);
    if ((c & 31) == 0) partial[c >> 5] = v;
    __syncthreads();
    if (c == 0) {
        float s = partial[0] + partial[1] + partial[2] + partial[3] + b3[0];
        out[g] = 1.f / (1.f + expf(-s));
    }
}

// ---------------- launch ----------------
extern "C" void kernel_launch(void* const* d_in, const int* in_sizes, int n_in,
                              void* d_out, int out_size)
{
    const float* x     = (const float*)d_in[0];
    const int*   ei    = (const int*)d_in[1];     // int32 (JAX x64 disabled)
    const int*   src   = ei;
    const int*   dst   = ei + NE;
    const int*   batch = (const int*)d_in[2];
    const float* convW = (const float*)d_in[3];
    const float* convB = (const float*)d_in[4];
    const float* W1    = (const float*)d_in[5];
    const float* b1    = (const float*)d_in[6];
    const float* W2    = (const float*)d_in[7];
    const float* b2    = (const float*)d_in[8];
    const float* W3    = (const float*)d_in[9];
    const float* b3    = (const float*)d_in[10];
    float* out = (float*)d_out;

    uint2 *hwb, *hbf;  uint4* wpk;
    cudaGetSymbolAddress((void**)&hwb, g_hwb);
    cudaGetSymbolAddress((void**)&hbf, g_hbf);
    cudaGetSymbolAddress((void**)&wpk, g_wpack);

    static bool attr_done = false;
    if (!attr_done) {
        cudaFuncSetAttribute(k_gemm_mma<0>, cudaFuncAttributeMaxDynamicSharedMemorySize, SMEM_MMA);
        cudaFuncSetAttribute(k_gemm_mma<1>, cudaFuncAttributeMaxDynamicSharedMemorySize, SMEM_MMA);
        attr_done = true;
    }

    // ---- setup: init (+Wpack), degree, scan, scatter ----
    k_init   <<<(NN + 255) / 256, 256>>>(convW);
    k_cnt    <<<(NE + 255) / 256, 256>>>(dst);
    k_scan1  <<<NSB, SCAN_B>>>();
    k_scan3  <<<NSB, SCAN_B>>>();
    k_scatter<<<(NE + 255) / 256, 256>>>(src, dst);

    // ---- 4 GCN layers ----
    uint32_t* hwb32 = reinterpret_cast<uint32_t*>(hwb);
    k_gemm_mma<0><<<NTILES, 256, SMEM_MMA>>>(x, wpk, hwb32, NN);
    k_agg<<<(NN * 32 + 255) / 256, 256>>>(hwb, convB, hbf);
    for (int l = 1; l < 4; l++) {
        k_gemm_mma<1><<<NTILES, 256, SMEM_MMA>>>(hbf, wpk + (size_t)l * 4096, hwb32, NN);
        k_agg<<<(NN * 32 + 255) / 256, 256>>>(hwb, convB + (size_t)l * DD, hbf);
    }

    // ---- pooling + fused MLP head ----
    k_pool<<<(NN + 127) / 128, 128>>>(reinterpret_cast<const uint32_t*>(hbf), batch);
    k_head<<<NG, 128>>>(W1, b1, W2, b2, W3, b3, out);
}

// round 11
// speedup vs baseline: 4.1304x; 1.0576x over previous
#include <cuda_runtime.h>
#include <cuda_bf16.h>
#include <math.h>
#include <cstdint>

#define NN   100000
#define NE   640000
#define DD   128
#define NG   512
#define SCAN_B 1024
#define NSB  ((NN + SCAN_B - 1) / SCAN_B)   // 98 scan blocks
#define NTILES ((NN + 255) / 256)           // 391 (256 rows per CTA)

// ---------------- scratch (no allocations allowed) ----------------
__device__ uint2 g_hwb[(size_t)NN * 32];    // h@W in bf16x2 (25.6MB)
__device__ uint2 g_hbf[(size_t)NN * 32];    // relu(agg+b) in bf16x2 (25.6MB)
__device__ float g_dinv[NN];
__device__ float g_dinv2[NN];
__device__ int   g_cnt [NN];
__device__ int   g_off [NN + 1];
__device__ int   g_cursor[NN];
__device__ int   g_csrc[NE];
__device__ float g_cw  [NE];
__device__ int   g_bsum[NSB];
__device__ float g_pooled[NG * DD];
// packed W fragments: [layer][n(128)][kk(8)][q(4)] uint4 = {hi@kb, hi@kb+4, lo@kb, lo@kb+4}
__device__ uint4 g_wpack[4 * 128 * 8 * 4];

// ---------------- smem layout for MMA GEMM ----------------
#define WPAD 36                          // uint4 per n-row in smem (padded from 32)
#define SMEM_MMA (128 * WPAD * 16)       // 73728

__device__ __forceinline__ void mma_bf16(float c[4], uint32_t a0, uint32_t a1,
                                         uint32_t a2, uint32_t a3,
                                         uint32_t b0, uint32_t b1) {
    asm volatile(
        "mma.sync.aligned.m16n8k16.row.col.f32.bf16.bf16.f32 "
        "{%0,%1,%2,%3}, {%4,%5,%6,%7}, {%8,%9}, {%0,%1,%2,%3};"
        : "+f"(c[0]), "+f"(c[1]), "+f"(c[2]), "+f"(c[3])
        : "r"(a0), "r"(a1), "r"(a2), "r"(a3), "r"(b0), "r"(b1));
}

__device__ __forceinline__ uint32_t bf2_of(float a, float b) {
    __nv_bfloat162 t = __float22bfloat162_rn(make_float2(a, b));
    return *reinterpret_cast<uint32_t*>(&t);
}
__device__ __forceinline__ float2 bf2f(uint32_t u) {
    __nv_bfloat162 h = *reinterpret_cast<__nv_bfloat162*>(&u);
    return __bfloat1622float2(h);
}

// ---------------- main-stream init: W pack + zero pooled ----------------
__global__ void k_wpack(const float* __restrict__ convW) {
    int idx = blockIdx.x * 256 + threadIdx.x;   // 16384 + 65536
    if (idx < NG * DD) g_pooled[idx] = 0.f;
    if (idx < 16384) {   // 4*128*8*4 W fragments
        int q  = idx & 3;
        int kk = (idx >> 2) & 7;
        int n  = (idx >> 5) & 127;
        int l  = idx >> 12;
        int k0 = kk * 16 + q * 2;
        const float* Wl = convW + (size_t)l * 16384;
        float w00 = Wl[(size_t)(k0    ) * 128 + n], w01 = Wl[(size_t)(k0 + 1) * 128 + n];
        float w10 = Wl[(size_t)(k0 + 8) * 128 + n], w11 = Wl[(size_t)(k0 + 9) * 128 + n];
        __nv_bfloat162 h0 = __float22bfloat162_rn(make_float2(w00, w01));
        __nv_bfloat162 h1 = __float22bfloat162_rn(make_float2(w10, w11));
        float2 f0 = __bfloat1622float2(h0), f1 = __bfloat1622float2(h1);
        uint4 v;
        v.x = *reinterpret_cast<uint32_t*>(&h0);
        v.y = *reinterpret_cast<uint32_t*>(&h1);
        v.z = bf2_of(w00 - f0.x, w01 - f0.y);
        v.w = bf2_of(w10 - f1.x, w11 - f1.y);
        g_wpack[idx] = v;
    }
}

// ---------------- side-stream CSR build ----------------
__global__ void k_cntzero() {
    int n = blockIdx.x * blockDim.x + threadIdx.x;
    if (n < NN) g_cnt[n] = 0;
}
__global__ void k_cnt(const int* __restrict__ dst) {
    int e = blockIdx.x * blockDim.x + threadIdx.x;
    if (e < NE) atomicAdd(&g_cnt[dst[e]], 1);
}
__global__ __launch_bounds__(SCAN_B) void k_scan1() {
    __shared__ int s[SCAN_B];
    int t = threadIdx.x;
    int i = blockIdx.x * SCAN_B + t;
    int v = (i < NN) ? g_cnt[i] : 0;
    if (i < NN) {
        float deg = (float)(v + 1);
        g_dinv[i]  = rsqrtf(deg);
        g_dinv2[i] = 1.0f / deg;
    }
    s[t] = v;
    __syncthreads();
    #pragma unroll
    for (int o = 1; o < SCAN_B; o <<= 1) {
        int x = (t >= o) ? s[t - o] : 0;
        __syncthreads();
        s[t] += x;
        __syncthreads();
    }
    if (i < NN) g_cnt[i] = s[t];
    if (t == SCAN_B - 1) g_bsum[blockIdx.x] = s[t];
}
__global__ __launch_bounds__(SCAN_B) void k_scan3() {
    __shared__ int partial[32];
    __shared__ int pre_s;
    int t = threadIdx.x;
    int v = (t < NSB && t < blockIdx.x) ? g_bsum[t] : 0;
    #pragma unroll
    for (int o = 16; o > 0; o >>= 1) v += __shfl_down_sync(0xffffffffu, v, o);
    if ((t & 31) == 0) partial[t >> 5] = v;
    __syncthreads();
    if (t == 0) {
        int s = 0;
        #pragma unroll
        for (int w = 0; w < SCAN_B / 32; w++) s += partial[w];
        pre_s = s;
    }
    __syncthreads();
    int pre = pre_s;
    int i = blockIdx.x * SCAN_B + t;
    if (i < NN) {
        int incl = g_cnt[i] + pre;
        g_off[i + 1] = incl;
        if (i + 1 < NN) g_cursor[i + 1] = incl;
        if (i == 0) { g_off[0] = 0; g_cursor[0] = 0; }
    }
}
__global__ void k_scatter(const int* __restrict__ src, const int* __restrict__ dst) {
    int e = blockIdx.x * blockDim.x + threadIdx.x;
    if (e < NE) {
        int s = src[e], t = dst[e];
        int p = atomicAdd(&g_cursor[t], 1);
        g_csrc[p] = s;
        g_cw[p]   = g_dinv[s] * g_dinv[t];
    }
}

// ============ tensor-core GEMM: hwb[M,128](bf16) = A @ W, 256 rows/CTA ============
// FUSE=0: A = fp32 input x (3-term split). FUSE=1: A = hbf (bf16, 2-term split).
template <int FUSE>
__global__ __launch_bounds__(512, 1) void k_gemm_mma(
    const void* __restrict__ Ain, const uint4* __restrict__ wp,
    uint32_t* __restrict__ outb, int M)
{
    extern __shared__ char smem[];
    uint4* Wp = reinterpret_cast<uint4*>(smem);
    int tid  = threadIdx.x;
    int wid  = tid >> 5;
    int lane = tid & 31;
    int m0   = blockIdx.x * 256;

    #pragma unroll
    for (int i = 0; i < 8; i++) {
        int idx = tid + i * 512;           // 4096 uint4
        int n = idx >> 5, r = idx & 31;
        Wp[n * WPAD + r] = wp[idx];
    }
    __syncthreads();

    int fr = lane >> 2;                    // 0..7
    int q  = lane & 3;                     // 0..3
    int r0 = m0 + wid * 16 + fr;
    int r1 = r0 + 8;
    bool ok0 = r0 < M, ok1 = r1 < M;

    float acc[16][4];
    #pragma unroll
    for (int ni = 0; ni < 16; ni++)
        #pragma unroll
        for (int p = 0; p < 4; p++) acc[ni][p] = 0.f;

    #pragma unroll
    for (int kk = 0; kk < 8; kk++) {
        int kw = kk * 8 + q;
        uint32_t ah[4], al[4];
        if (FUSE) {
            const uint32_t* H = reinterpret_cast<const uint32_t*>(Ain);
            ah[0] = ok0 ? H[(size_t)r0 * 64 + kw]     : 0u;
            ah[2] = ok0 ? H[(size_t)r0 * 64 + kw + 4] : 0u;
            ah[1] = ok1 ? H[(size_t)r1 * 64 + kw]     : 0u;
            ah[3] = ok1 ? H[(size_t)r1 * 64 + kw + 4] : 0u;
        } else {
            const float2* A2 = reinterpret_cast<const float2*>(Ain);
            float2 v00 = make_float2(0.f, 0.f), v01 = v00, v10 = v00, v11 = v00;
            if (ok0) { v00 = A2[(size_t)r0 * 64 + kw]; v01 = A2[(size_t)r0 * 64 + kw + 4]; }
            if (ok1) { v10 = A2[(size_t)r1 * 64 + kw]; v11 = A2[(size_t)r1 * 64 + kw + 4]; }
            __nv_bfloat162 h; float2 f;
            h = __float22bfloat162_rn(v00); f = __bfloat1622float2(h);
            ah[0] = *reinterpret_cast<uint32_t*>(&h); al[0] = bf2_of(v00.x - f.x, v00.y - f.y);
            h = __float22bfloat162_rn(v10); f = __bfloat1622float2(h);
            ah[1] = *reinterpret_cast<uint32_t*>(&h); al[1] = bf2_of(v10.x - f.x, v10.y - f.y);
            h = __float22bfloat162_rn(v01); f = __bfloat1622float2(h);
            ah[2] = *reinterpret_cast<uint32_t*>(&h); al[2] = bf2_of(v01.x - f.x, v01.y - f.y);
            h = __float22bfloat162_rn(v11); f = __bfloat1622float2(h);
            ah[3] = *reinterpret_cast<uint32_t*>(&h); al[3] = bf2_of(v11.x - f.x, v11.y - f.y);
        }
        #pragma unroll
        for (int ni = 0; ni < 16; ni++) {
            int n = ni * 8 + fr;
            uint4 b = Wp[n * WPAD + kk * 4 + q];
            mma_bf16(acc[ni], ah[0], ah[1], ah[2], ah[3], b.x, b.y);      // A_hi * W_hi
            mma_bf16(acc[ni], ah[0], ah[1], ah[2], ah[3], b.z, b.w);      // A_hi * W_lo
            if (!FUSE)
                mma_bf16(acc[ni], al[0], al[1], al[2], al[3], b.x, b.y);  // A_lo * W_hi
        }
    }

    #pragma unroll
    for (int ni = 0; ni < 16; ni++) {
        int cw = ni * 4 + q;
        if (ok0) outb[(size_t)r0 * 64 + cw] = bf2_of(acc[ni][0], acc[ni][1]);
        if (ok1) outb[(size_t)r1 * 64 + cw] = bf2_of(acc[ni][2], acc[ni][3]);
    }
}

// ---- CSR aggregation, 4-way unrolled; fused bias+relu, bf16 out ----
__global__ __launch_bounds__(256) void k_agg(const uint2* __restrict__ hwb,
                                             const float* __restrict__ bias,
                                             uint2* __restrict__ hbf)
{
    int gid  = blockIdx.x * blockDim.x + threadIdx.x;
    int n    = gid >> 5;
    int lane = threadIdx.x & 31;
    if (n >= NN) return;
    uint2 sv = hwb[(size_t)n * 32 + lane];
    float2 s0 = bf2f(sv.x), s1 = bf2f(sv.y);
    float w = g_dinv2[n];
    float a0 = s0.x * w, a1 = s0.y * w, a2 = s1.x * w, a3 = s1.y * w;
    int i = g_off[n], end = g_off[n + 1];

    for (; i + 4 <= end; i += 4) {
        int   s0i = g_csrc[i],     s1i = g_csrc[i + 1];
        int   s2i = g_csrc[i + 2], s3i = g_csrc[i + 3];
        float w0 = g_cw[i],     w1 = g_cw[i + 1];
        float w2 = g_cw[i + 2], w3 = g_cw[i + 3];
        uint2 v0 = __ldg(&hwb[(size_t)s0i * 32 + lane]);
        uint2 v1 = __ldg(&hwb[(size_t)s1i * 32 + lane]);
        uint2 v2 = __ldg(&hwb[(size_t)s2i * 32 + lane]);
        uint2 v3 = __ldg(&hwb[(size_t)s3i * 32 + lane]);
        float2 f;
        f = bf2f(v0.x); a0 = fmaf(w0, f.x, a0); a1 = fmaf(w0, f.y, a1);
        f = bf2f(v0.y); a2 = fmaf(w0, f.x, a2); a3 = fmaf(w0, f.y, a3);
        f = bf2f(v1.x); a0 = fmaf(w1, f.x, a0); a1 = fmaf(w1, f.y, a1);
        f = bf2f(v1.y); a2 = fmaf(w1, f.x, a2); a3 = fmaf(w1, f.y, a3);
        f = bf2f(v2.x); a0 = fmaf(w2, f.x, a0); a1 = fmaf(w2, f.y, a1);
        f = bf2f(v2.y); a2 = fmaf(w2, f.x, a2); a3 = fmaf(w2, f.y, a3);
        f = bf2f(v3.x); a0 = fmaf(w3, f.x, a0); a1 = fmaf(w3, f.y, a1);
        f = bf2f(v3.y); a2 = fmaf(w3, f.x, a2); a3 = fmaf(w3, f.y, a3);
    }
    for (; i < end; i++) {
        int   sn = g_csrc[i];
        float we = g_cw[i];
        uint2 v  = __ldg(&hwb[(size_t)sn * 32 + lane]);
        float2 f0 = bf2f(v.x), f1 = bf2f(v.y);
        a0 = fmaf(we, f0.x, a0);
        a1 = fmaf(we, f0.y, a1);
        a2 = fmaf(we, f1.x, a2);
        a3 = fmaf(we, f1.y, a3);
    }
    float4 b4 = reinterpret_cast<const float4*>(bias)[lane];
    uint2 o;
    o.x = bf2_of(fmaxf(a0 + b4.x, 0.f), fmaxf(a1 + b4.y, 0.f));
    o.y = bf2_of(fmaxf(a2 + b4.z, 0.f), fmaxf(a3 + b4.w, 0.f));
    hbf[(size_t)n * 32 + lane] = o;
}

// ---------------- pooling (batch is sorted); h = packed bf16 ----------------
__global__ void k_pool(const uint32_t* __restrict__ hp,
                       const int* __restrict__ batch)
{
    int d  = threadIdx.x;
    int n0 = blockIdx.x * 128;
    int n1 = n0 + 128; if (n1 > NN) n1 = NN;
    if (n0 >= NN) return;
    int  wsel = d >> 1;
    bool hi   = d & 1;
    float acc = 0.f;
    int gprev = batch[n0];
    for (int n = n0; n < n1; n++) {
        int g = batch[n];
        if (g != gprev) {
            atomicAdd(&g_pooled[gprev * 128 + d], acc);
            acc = 0.f;
            gprev = g;
        }
        float2 hl = bf2f(hp[(size_t)n * 64 + wsel]);
        acc += hi ? hl.y : hl.x;
    }
    atomicAdd(&g_pooled[gprev * 128 + d], acc);
}

// ---------------- fused MLP head ----------------
__global__ void k_head(const float* __restrict__ W1, const float* __restrict__ b1,
                       const float* __restrict__ W2, const float* __restrict__ b2,
                       const float* __restrict__ W3, const float* __restrict__ b3,
                       float* __restrict__ out)
{
    __shared__ float buf[128];
    __shared__ float partial[4];
    int g = blockIdx.x, c = threadIdx.x;
    buf[c] = g_pooled[g * 128 + c];
    __syncthreads();
    float acc = b1[c];
    #pragma unroll 8
    for (int k = 0; k < 128; k++)
        acc = fmaf(buf[k], W1[k * 128 + c], acc);
    float z1 = fmaxf(acc, 0.f);
    __syncthreads();
    buf[c] = z1;
    __syncthreads();
    acc = b2[c];
    #pragma unroll 8
    for (int k = 0; k < 128; k++)
        acc = fmaf(buf[k], W2[k * 128 + c], acc);
    float z2 = fmaxf(acc, 0.f);
    float v = z2 * W3[c];
    #pragma unroll
    for (int o = 16; o > 0; o >>= 1) v += __shfl_down_sync(0xffffffffu, v, o);
    if ((c & 31) == 0) partial[c >> 5] = v;
    __syncthreads();
    if (c == 0) {
        float s = partial[0] + partial[1] + partial[2] + partial[3] + b3[0];
        out[g] = 1.f / (1.f + expf(-s));
    }
}

// ---------------- launch ----------------
extern "C" void kernel_launch(void* const* d_in, const int* in_sizes, int n_in,
                              void* d_out, int out_size)
{
    const float* x     = (const float*)d_in[0];
    const int*   ei    = (const int*)d_in[1];     // int32 (JAX x64 disabled)
    const int*   src   = ei;
    const int*   dst   = ei + NE;
    const int*   batch = (const int*)d_in[2];
    const float* convW = (const float*)d_in[3];
    const float* convB = (const float*)d_in[4];
    const float* W1    = (const float*)d_in[5];
    const float* b1    = (const float*)d_in[6];
    const float* W2    = (const float*)d_in[7];
    const float* b2    = (const float*)d_in[8];
    const float* W3    = (const float*)d_in[9];
    const float* b3    = (const float*)d_in[10];
    float* out = (float*)d_out;

    uint2 *hwb, *hbf;  uint4* wpk;
    cudaGetSymbolAddress((void**)&hwb, g_hwb);
    cudaGetSymbolAddress((void**)&hbf, g_hbf);
    cudaGetSymbolAddress((void**)&wpk, g_wpack);

    static cudaStream_t s2;
    static cudaEvent_t evFork, evJoin;
    static bool once = false;
    if (!once) {
        cudaFuncSetAttribute(k_gemm_mma<0>, cudaFuncAttributeMaxDynamicSharedMemorySize, SMEM_MMA);
        cudaFuncSetAttribute(k_gemm_mma<1>, cudaFuncAttributeMaxDynamicSharedMemorySize, SMEM_MMA);
        cudaStreamCreateWithFlags(&s2, cudaStreamNonBlocking);
        cudaEventCreateWithFlags(&evFork, cudaEventDisableTiming);
        cudaEventCreateWithFlags(&evJoin, cudaEventDisableTiming);
        once = true;
    }

    // ---- fork: CSR build on side stream, W pack + gemm0 on main ----
    cudaEventRecord(evFork, 0);
    cudaStreamWaitEvent(s2, evFork, 0);

    k_cntzero<<<(NN + 255) / 256, 256, 0, s2>>>();
    k_cnt    <<<(NE + 255) / 256, 256, 0, s2>>>(dst);
    k_scan1  <<<NSB, SCAN_B, 0, s2>>>();
    k_scan3  <<<NSB, SCAN_B, 0, s2>>>();
    k_scatter<<<(NE + 255) / 256, 256, 0, s2>>>(src, dst);
    cudaEventRecord(evJoin, s2);

    uint32_t* hwb32 = reinterpret_cast<uint32_t*>(hwb);
    k_wpack<<<(NG * DD + 255) / 256, 256>>>(convW);
    k_gemm_mma<0><<<NTILES, 512, SMEM_MMA>>>(x, wpk, hwb32, NN);

    // ---- join, then the remaining dependent chain ----
    cudaStreamWaitEvent(0, evJoin, 0);
    k_agg<<<(NN * 32 + 255) / 256, 256>>>(hwb, convB, hbf);
    for (int l = 1; l < 4; l++) {
        k_gemm_mma<1><<<NTILES, 512, SMEM_MMA>>>(hbf, wpk + (size_t)l * 4096, hwb32, NN);
        k_agg<<<(NN * 32 + 255) / 256, 256>>>(hwb, convB + (size_t)l * DD, hbf);
    }

    // ---- pooling + fused MLP head ----
    k_pool<<<(NN + 127) / 128, 128>>>(reinterpret_cast<const uint32_t*>(hbf), batch);
    k_head<<<NG, 128>>>(W1, b1, W2, b2, W3, b3, out);
}